// round 14
// baseline (speedup 1.0000x reference)
#include <cuda_runtime.h>
#include <math.h>

#define NRBF  20
#define MAXN  10000
#define MAXE  320000
#define NLAYERS 3
#define EB 16   // edge batch staged through smem

typedef unsigned long long u64;

// ---------------- packed f32x2 helpers (sm_103a FFMA2) ----------------
__device__ __forceinline__ u64 ffma2(u64 a, u64 b, u64 c) {
    u64 d;
    asm("fma.rn.f32x2 %0, %1, %2, %3;" : "=l"(d) : "l"(a), "l"(b), "l"(c));
    return d;
}
__device__ __forceinline__ u64 pack2(float lo, float hi) {
    u64 d;
    asm("mov.b64 %0, {%1, %2};" : "=l"(d) : "f"(lo), "f"(hi));
    return d;
}
__device__ __forceinline__ float2 unpack2(u64 v) {
    float lo, hi;
    asm("mov.b64 {%0, %1}, %2;" : "=f"(lo), "=f"(hi) : "l"(v));
    return make_float2(lo, hi);
}

// ---------------- device scratch (allocation-free) ----------------
__device__ float g_dir  [MAXE * 3];
__device__ float g_phif [MAXE * NRBF];   // phi * fcut
__device__ float g_fcut [MAXE];
__device__ int   g_rowptr[MAXN + 1];
__device__ float g_x    [MAXN * 512];    // interaction x: [N][128][4] (xq,xR,xM,pad); mixing x2 uses [N][384]
__device__ float g_h    [MAXN * 128];
__device__ float g_muA  [MAXN * 384];
__device__ float g_mumix[MAXN * 768];    // [N,3,256]

// ---------------- fused setup: edge geometry/RBF + rowptr + q init ----------
__global__ void setup_kernel(const float* __restrict__ r_ij,
                             const int* __restrict__ idx_i,
                             const int* __restrict__ an,
                             const float* __restrict__ emb,
                             float* __restrict__ q,
                             int E, int N) {
    int t = blockIdx.x * blockDim.x + threadIdx.x;
    if (t < E) {
        int e = t;
        float x = r_ij[e * 3 + 0];
        float y = r_ij[e * 3 + 1];
        float z = r_ij[e * 3 + 2];
        float d = sqrtf(x * x + y * y + z * z);
        float inv = 1.0f / d;
        g_dir[e * 3 + 0] = x * inv;
        g_dir[e * 3 + 1] = y * inv;
        g_dir[e * 3 + 2] = z * inv;
        float fc = (d < 5.0f) ? 0.5f * (cosf(d * 0.62831853071795864769f) + 1.0f) : 0.0f;
        g_fcut[e] = fc;
        const float delta = 5.0f / 19.0f;
        const float coeff = -0.5f / (delta * delta);
#pragma unroll
        for (int r = 0; r < NRBF; r++) {
            float diff = d - delta * (float)r;
            g_phif[e * NRBF + r] = expf(coeff * diff * diff) * fc;
        }
    }
    if (t < N * 128) {
        int n = t >> 7, c = t & 127;
        q[t] = emb[an[n] * 128 + c];
    }
    if (t <= N) {
        int lo = 0, hi = E;
        while (lo < hi) {
            int mid = (lo + hi) >> 1;
            if (idx_i[mid] < t) lo = mid + 1; else hi = mid;
        }
        g_rowptr[t] = lo;
    }
}

// ---------------- double-buffered fp32 GEMM: C = act(A[M,K] @ W[K,N] + bias) --
// BM=BN=64, BK=32, 256 threads, 4x4 per thread. N % 64 == 0, K % 32 == 0.
// ILV=1: interleaved epilogue C[r*512 + (col&127)*4 + (col>>7)] (edge-x layout).
template <int ACT, int ILV>
__global__ void __launch_bounds__(256)
gemm64(const float* __restrict__ A, const float* __restrict__ W,
       const float* __restrict__ bias, float* __restrict__ C,
       int M, int N, int K) {
    __shared__ float As[2][32][68];
    __shared__ float Bs[2][32][68];
    const int tid  = threadIdx.x;
    const int row0 = blockIdx.y * 64;
    const int col0 = blockIdx.x * 64;
    const int tx = tid & 15, ty = tid >> 4;

    int ar0 = tid >> 3,          ak0 = (tid & 7) << 2;
    int ar1 = (tid + 256) >> 3;
    int br0 = tid >> 4,          bc0 = (tid & 15) << 2;
    int br1 = (tid + 256) >> 4;

    const bool av0 = (row0 + ar0) < M;
    const bool av1 = (row0 + ar1) < M;
    const float* Ap0 = A + (size_t)(row0 + ar0) * K + ak0;
    const float* Ap1 = A + (size_t)(row0 + ar1) * K + ak0;
    const float* Wp0 = W + (size_t)br0 * N + col0 + bc0;
    const float* Wp1 = W + (size_t)br1 * N + col0 + bc0;

    float4 a0 = av0 ? *(const float4*)Ap0 : make_float4(0.f, 0.f, 0.f, 0.f);
    float4 a1 = av1 ? *(const float4*)Ap1 : make_float4(0.f, 0.f, 0.f, 0.f);
    float4 b0 = *(const float4*)Wp0;
    float4 b1 = *(const float4*)Wp1;
    As[0][ak0 + 0][ar0] = a0.x; As[0][ak0 + 1][ar0] = a0.y;
    As[0][ak0 + 2][ar0] = a0.z; As[0][ak0 + 3][ar0] = a0.w;
    As[0][ak0 + 0][ar1] = a1.x; As[0][ak0 + 1][ar1] = a1.y;
    As[0][ak0 + 2][ar1] = a1.z; As[0][ak0 + 3][ar1] = a1.w;
    *(float4*)&Bs[0][br0][bc0] = b0;
    *(float4*)&Bs[0][br1][bc0] = b1;
    __syncthreads();

    float acc[4][4];
#pragma unroll
    for (int i = 0; i < 4; i++)
#pragma unroll
        for (int j = 0; j < 4; j++) acc[i][j] = 0.0f;

    int buf = 0;
    for (int k0 = 32; k0 < K; k0 += 32) {
        a0 = av0 ? *(const float4*)(Ap0 + k0) : make_float4(0.f, 0.f, 0.f, 0.f);
        a1 = av1 ? *(const float4*)(Ap1 + k0) : make_float4(0.f, 0.f, 0.f, 0.f);
        b0 = *(const float4*)(Wp0 + (size_t)k0 * N);
        b1 = *(const float4*)(Wp1 + (size_t)k0 * N);
#pragma unroll
        for (int kk = 0; kk < 32; kk++) {
            float4 a = *(const float4*)&As[buf][kk][ty << 2];
            float4 b = *(const float4*)&Bs[buf][kk][tx << 2];
            acc[0][0] = fmaf(a.x, b.x, acc[0][0]); acc[0][1] = fmaf(a.x, b.y, acc[0][1]);
            acc[0][2] = fmaf(a.x, b.z, acc[0][2]); acc[0][3] = fmaf(a.x, b.w, acc[0][3]);
            acc[1][0] = fmaf(a.y, b.x, acc[1][0]); acc[1][1] = fmaf(a.y, b.y, acc[1][1]);
            acc[1][2] = fmaf(a.y, b.z, acc[1][2]); acc[1][3] = fmaf(a.y, b.w, acc[1][3]);
            acc[2][0] = fmaf(a.z, b.x, acc[2][0]); acc[2][1] = fmaf(a.z, b.y, acc[2][1]);
            acc[2][2] = fmaf(a.z, b.z, acc[2][2]); acc[2][3] = fmaf(a.z, b.w, acc[2][3]);
            acc[3][0] = fmaf(a.w, b.x, acc[3][0]); acc[3][1] = fmaf(a.w, b.y, acc[3][1]);
            acc[3][2] = fmaf(a.w, b.z, acc[3][2]); acc[3][3] = fmaf(a.w, b.w, acc[3][3]);
        }
        buf ^= 1;
        As[buf][ak0 + 0][ar0] = a0.x; As[buf][ak0 + 1][ar0] = a0.y;
        As[buf][ak0 + 2][ar0] = a0.z; As[buf][ak0 + 3][ar0] = a0.w;
        As[buf][ak0 + 0][ar1] = a1.x; As[buf][ak0 + 1][ar1] = a1.y;
        As[buf][ak0 + 2][ar1] = a1.z; As[buf][ak0 + 3][ar1] = a1.w;
        *(float4*)&Bs[buf][br0][bc0] = b0;
        *(float4*)&Bs[buf][br1][bc0] = b1;
        __syncthreads();
    }
#pragma unroll
    for (int kk = 0; kk < 32; kk++) {
        float4 a = *(const float4*)&As[buf][kk][ty << 2];
        float4 b = *(const float4*)&Bs[buf][kk][tx << 2];
        acc[0][0] = fmaf(a.x, b.x, acc[0][0]); acc[0][1] = fmaf(a.x, b.y, acc[0][1]);
        acc[0][2] = fmaf(a.x, b.z, acc[0][2]); acc[0][3] = fmaf(a.x, b.w, acc[0][3]);
        acc[1][0] = fmaf(a.y, b.x, acc[1][0]); acc[1][1] = fmaf(a.y, b.y, acc[1][1]);
        acc[1][2] = fmaf(a.y, b.z, acc[1][2]); acc[1][3] = fmaf(a.y, b.w, acc[1][3]);
        acc[2][0] = fmaf(a.z, b.x, acc[2][0]); acc[2][1] = fmaf(a.z, b.y, acc[2][1]);
        acc[2][2] = fmaf(a.z, b.z, acc[2][2]); acc[2][3] = fmaf(a.z, b.w, acc[2][3]);
        acc[3][0] = fmaf(a.w, b.x, acc[3][0]); acc[3][1] = fmaf(a.w, b.y, acc[3][1]);
        acc[3][2] = fmaf(a.w, b.z, acc[3][2]); acc[3][3] = fmaf(a.w, b.w, acc[3][3]);
    }

    float bj[4] = {0.f, 0.f, 0.f, 0.f};
    if (bias) {
#pragma unroll
        for (int j = 0; j < 4; j++) bj[j] = bias[col0 + (tx << 2) + j];
    }
#pragma unroll
    for (int i = 0; i < 4; i++) {
        int r = row0 + (ty << 2) + i;
        if (r >= M) continue;
        if (ILV == 0) {
            float4 v;
            float* pv = &v.x;
#pragma unroll
            for (int j = 0; j < 4; j++) {
                float val = acc[i][j] + bj[j];
                if (ACT == 1) val = val / (1.0f + expf(-val));
                pv[j] = val;
            }
            *(float4*)&C[(size_t)r * N + col0 + (tx << 2)] = v;
        } else {
#pragma unroll
            for (int j = 0; j < 4; j++) {
                float val = acc[i][j] + bj[j];
                int col = col0 + (tx << 2) + j;
                C[(size_t)r * 512 + ((col & 127) << 2) + (col >> 7)] = val;
            }
        }
    }
}

// ---------------- ctx A-operand builder -------------------------------------
__device__ __forceinline__ float4 ctx_load(const float* __restrict__ q,
                                           const float* __restrict__ mumix,
                                           int n, int k, bool valid) {
    if (!valid) return make_float4(0.f, 0.f, 0.f, 0.f);
    if (k < 128) return *(const float4*)&q[(size_t)n * 128 + k];
    int c = k - 128;
    const float* b = mumix + (size_t)n * 768;
    float4 v0 = *(const float4*)&b[c];
    float4 v1 = *(const float4*)&b[256 + c];
    float4 v2 = *(const float4*)&b[512 + c];
    float4 r;
    r.x = sqrtf(v0.x * v0.x + v1.x * v1.x + v2.x * v2.x + 1e-8f);
    r.y = sqrtf(v0.y * v0.y + v1.y * v1.y + v2.y * v2.y + 1e-8f);
    r.z = sqrtf(v0.z * v0.z + v1.z * v1.z + v2.z * v2.z + 1e-8f);
    r.w = sqrtf(v0.w * v0.w + v1.w * v1.w + v2.w * v2.w + 1e-8f);
    return r;
}

// ---------------- ctx GEMM: h = silu(ctx @ W + b), ctx built on the fly ------
__global__ void __launch_bounds__(256)
gemm_ctx(const float* __restrict__ q, const float* __restrict__ mumix,
         const float* __restrict__ W, const float* __restrict__ bias,
         float* __restrict__ C, int M) {
    const int Nn = 128, K = 256;
    __shared__ float As[2][32][68];
    __shared__ float Bs[2][32][68];
    const int tid  = threadIdx.x;
    const int row0 = blockIdx.y * 64;
    const int col0 = blockIdx.x * 64;
    const int tx = tid & 15, ty = tid >> 4;

    int ar0 = tid >> 3,          ak0 = (tid & 7) << 2;
    int ar1 = (tid + 256) >> 3;
    int br0 = tid >> 4,          bc0 = (tid & 15) << 2;
    int br1 = (tid + 256) >> 4;

    const bool av0 = (row0 + ar0) < M;
    const bool av1 = (row0 + ar1) < M;
    const float* Wp0 = W + (size_t)br0 * Nn + col0 + bc0;
    const float* Wp1 = W + (size_t)br1 * Nn + col0 + bc0;

    float4 a0 = ctx_load(q, mumix, row0 + ar0, ak0, av0);
    float4 a1 = ctx_load(q, mumix, row0 + ar1, ak0, av1);
    float4 b0 = *(const float4*)Wp0;
    float4 b1 = *(const float4*)Wp1;
    As[0][ak0 + 0][ar0] = a0.x; As[0][ak0 + 1][ar0] = a0.y;
    As[0][ak0 + 2][ar0] = a0.z; As[0][ak0 + 3][ar0] = a0.w;
    As[0][ak0 + 0][ar1] = a1.x; As[0][ak0 + 1][ar1] = a1.y;
    As[0][ak0 + 2][ar1] = a1.z; As[0][ak0 + 3][ar1] = a1.w;
    *(float4*)&Bs[0][br0][bc0] = b0;
    *(float4*)&Bs[0][br1][bc0] = b1;
    __syncthreads();

    float acc[4][4];
#pragma unroll
    for (int i = 0; i < 4; i++)
#pragma unroll
        for (int j = 0; j < 4; j++) acc[i][j] = 0.0f;

    int buf = 0;
    for (int k0 = 32; k0 < K; k0 += 32) {
        a0 = ctx_load(q, mumix, row0 + ar0, k0 + ak0, av0);
        a1 = ctx_load(q, mumix, row0 + ar1, k0 + ak0, av1);
        b0 = *(const float4*)(Wp0 + (size_t)k0 * Nn);
        b1 = *(const float4*)(Wp1 + (size_t)k0 * Nn);
#pragma unroll
        for (int kk = 0; kk < 32; kk++) {
            float4 a = *(const float4*)&As[buf][kk][ty << 2];
            float4 b = *(const float4*)&Bs[buf][kk][tx << 2];
            acc[0][0] = fmaf(a.x, b.x, acc[0][0]); acc[0][1] = fmaf(a.x, b.y, acc[0][1]);
            acc[0][2] = fmaf(a.x, b.z, acc[0][2]); acc[0][3] = fmaf(a.x, b.w, acc[0][3]);
            acc[1][0] = fmaf(a.y, b.x, acc[1][0]); acc[1][1] = fmaf(a.y, b.y, acc[1][1]);
            acc[1][2] = fmaf(a.y, b.z, acc[1][2]); acc[1][3] = fmaf(a.y, b.w, acc[1][3]);
            acc[2][0] = fmaf(a.z, b.x, acc[2][0]); acc[2][1] = fmaf(a.z, b.y, acc[2][1]);
            acc[2][2] = fmaf(a.z, b.z, acc[2][2]); acc[2][3] = fmaf(a.z, b.w, acc[2][3]);
            acc[3][0] = fmaf(a.w, b.x, acc[3][0]); acc[3][1] = fmaf(a.w, b.y, acc[3][1]);
            acc[3][2] = fmaf(a.w, b.z, acc[3][2]); acc[3][3] = fmaf(a.w, b.w, acc[3][3]);
        }
        buf ^= 1;
        As[buf][ak0 + 0][ar0] = a0.x; As[buf][ak0 + 1][ar0] = a0.y;
        As[buf][ak0 + 2][ar0] = a0.z; As[buf][ak0 + 3][ar0] = a0.w;
        As[buf][ak0 + 0][ar1] = a1.x; As[buf][ak0 + 1][ar1] = a1.y;
        As[buf][ak0 + 2][ar1] = a1.z; As[buf][ak0 + 3][ar1] = a1.w;
        *(float4*)&Bs[buf][br0][bc0] = b0;
        *(float4*)&Bs[buf][br1][bc0] = b1;
        __syncthreads();
    }
#pragma unroll
    for (int kk = 0; kk < 32; kk++) {
        float4 a = *(const float4*)&As[buf][kk][ty << 2];
        float4 b = *(const float4*)&Bs[buf][kk][tx << 2];
        acc[0][0] = fmaf(a.x, b.x, acc[0][0]); acc[0][1] = fmaf(a.x, b.y, acc[0][1]);
        acc[0][2] = fmaf(a.x, b.z, acc[0][2]); acc[0][3] = fmaf(a.x, b.w, acc[0][3]);
        acc[1][0] = fmaf(a.y, b.x, acc[1][0]); acc[1][1] = fmaf(a.y, b.y, acc[1][1]);
        acc[1][2] = fmaf(a.y, b.z, acc[1][2]); acc[1][3] = fmaf(a.y, b.w, acc[1][3]);
        acc[2][0] = fmaf(a.z, b.x, acc[2][0]); acc[2][1] = fmaf(a.z, b.y, acc[2][1]);
        acc[2][2] = fmaf(a.z, b.z, acc[2][2]); acc[2][3] = fmaf(a.z, b.w, acc[2][3]);
        acc[3][0] = fmaf(a.w, b.x, acc[3][0]); acc[3][1] = fmaf(a.w, b.y, acc[3][1]);
        acc[3][2] = fmaf(a.w, b.z, acc[3][2]); acc[3][3] = fmaf(a.w, b.w, acc[3][3]);
    }

    float bj[4];
#pragma unroll
    for (int j = 0; j < 4; j++) bj[j] = bias[col0 + (tx << 2) + j];
#pragma unroll
    for (int i = 0; i < 4; i++) {
        int r = row0 + (ty << 2) + i;
        if (r >= M) continue;
        float4 v;
        float* pv = &v.x;
#pragma unroll
        for (int j = 0; j < 4; j++) {
            float val = acc[i][j] + bj[j];
            val = val / (1.0f + expf(-val));
            pv[j] = val;
        }
        *(float4*)&C[(size_t)r * Nn + col0 + (tx << 2)] = v;
    }
}

// ---------------- edge message + segment-sum kernel (general layers) --------
// ROUND-11 PROVEN pipeline (staged pp[10]); x gathered via ONE LDG.128 from
// the interleaved [N][128][4] layout.
__global__ void __launch_bounds__(128)
edge_kernel(const float* __restrict__ x,
            float* __restrict__ q,
            const float* __restrict__ mu_in,
            float* __restrict__ mu_out,
            const int* __restrict__ idx_j,
            const float* __restrict__ filt_W,
            const float* __restrict__ filt_b,
            int layer, int N) {
    __shared__ __align__(16) float s_phif[EB * NRBF];
    __shared__ float s_dir[EB * 3];
    __shared__ float s_fcut[EB];
    __shared__ int   s_idx[EB];

    int c = threadIdx.x;   // 0..127
    int layOff = layer * 384;
    u64 WQ2[10], WR2[10], WM2[10];
#pragma unroll
    for (int r2 = 0; r2 < 10; r2++) {
        const float* f0 = &filt_W[(2 * r2)     * (NLAYERS * 384) + layOff];
        const float* f1 = &filt_W[(2 * r2 + 1) * (NLAYERS * 384) + layOff];
        WQ2[r2] = pack2(f0[c],       f1[c]);
        WR2[r2] = pack2(f0[128 + c], f1[128 + c]);
        WM2[r2] = pack2(f0[256 + c], f1[256 + c]);
    }
    float FBq = filt_b[layOff + c];
    float FBr = filt_b[layOff + 128 + c];
    float FBm = filt_b[layOff + 256 + c];

    int node = blockIdx.x;
    if (node >= N) return;
    int e0 = g_rowptr[node], e1 = g_rowptr[node + 1];
    float accq = 0.f, am0 = 0.f, am1 = 0.f, am2 = 0.f;

    for (int eb = e0; eb < e1; eb += EB) {
        int cnt = min(EB, e1 - eb);
        __syncthreads();
        if (c < cnt * 5)
            *(float4*)&s_phif[c << 2] = *(const float4*)&g_phif[(size_t)eb * NRBF + (c << 2)];
        int t = c - 80;
        if (t >= 0 && t < cnt * 3)
            s_dir[t] = g_dir[(size_t)eb * 3 + t];
        if (c < cnt) s_fcut[c] = g_fcut[eb + c];
        int u = c - 16;
        if (u >= 0 && u < cnt) s_idx[u] = idx_j[eb + u];
        __syncthreads();

        for (int i = 0; i < cnt; i++) {
            int j = s_idx[i];
            float4 xv = *(const float4*)&x[(size_t)j * 512 + (c << 2)];
            const float* mj = &mu_in[(size_t)j * 384];
            float m0 = mj[c], m1 = mj[128 + c], m2 = mj[256 + c];
            u64 pp[10];
            const ulonglong2* pv = (const ulonglong2*)&s_phif[i * NRBF];
#pragma unroll
            for (int v = 0; v < 5; v++) {
                ulonglong2 tt2 = pv[v];
                pp[2 * v]     = tt2.x;
                pp[2 * v + 1] = tt2.y;
            }
            u64 aq = 0ull, ar = 0ull, am = 0ull;
#pragma unroll
            for (int r = 0; r < 10; r++) {
                aq = ffma2(pp[r], WQ2[r], aq);
                ar = ffma2(pp[r], WR2[r], ar);
                am = ffma2(pp[r], WM2[r], am);
            }
            float fc = s_fcut[i];
            float2 fq = unpack2(aq), fr = unpack2(ar), fm = unpack2(am);
            float Wq = fmaf(fc, FBq, fq.x + fq.y);
            float Wr = fmaf(fc, FBr, fr.x + fr.y);
            float Wm = fmaf(fc, FBm, fm.x + fm.y);

            float d0 = s_dir[i * 3 + 0], d1 = s_dir[i * 3 + 1], d2 = s_dir[i * 3 + 2];
            accq = fmaf(Wq, xv.x, accq);
            float tt  = Wr * xv.y;
            float wmx = Wm * xv.z;
            am0 = fmaf(tt, d0, fmaf(wmx, m0, am0));
            am1 = fmaf(tt, d1, fmaf(wmx, m1, am1));
            am2 = fmaf(tt, d2, fmaf(wmx, m2, am2));
        }
    }
    q[(size_t)node * 128 + c] += accq;
    size_t mb = (size_t)node * 384;
    mu_out[mb + c]       = mu_in[mb + c]       + am0;
    mu_out[mb + 128 + c] = mu_in[mb + 128 + c] + am1;
    mu_out[mb + 256 + c] = mu_in[mb + 256 + c] + am2;
}

// ---------------- layer-0 edge kernel: mu_in == 0 everywhere ----------------
// ROUND-12 PROVEN inline-LDS variant; x gathered via ONE LDG.128.
__global__ void __launch_bounds__(128)
edge0_kernel(const float* __restrict__ x,
             float* __restrict__ q,
             float* __restrict__ mu_out,
             const int* __restrict__ idx_j,
             const float* __restrict__ filt_W,
             const float* __restrict__ filt_b,
             int N) {
    __shared__ __align__(16) float s_phif[EB * NRBF];
    __shared__ float s_dir[EB * 3];
    __shared__ float s_fcut[EB];
    __shared__ int   s_idx[EB];

    int c = threadIdx.x;
    u64 WQ2[10], WR2[10];
#pragma unroll
    for (int r2 = 0; r2 < 10; r2++) {
        const float* f0 = &filt_W[(2 * r2)     * (NLAYERS * 384)];
        const float* f1 = &filt_W[(2 * r2 + 1) * (NLAYERS * 384)];
        WQ2[r2] = pack2(f0[c],       f1[c]);
        WR2[r2] = pack2(f0[128 + c], f1[128 + c]);
    }
    float FBq = filt_b[c];
    float FBr = filt_b[128 + c];

    int node = blockIdx.x;
    if (node >= N) return;
    int e0 = g_rowptr[node], e1 = g_rowptr[node + 1];
    float accq = 0.f, am0 = 0.f, am1 = 0.f, am2 = 0.f;

    for (int eb = e0; eb < e1; eb += EB) {
        int cnt = min(EB, e1 - eb);
        __syncthreads();
        if (c < cnt * 5)
            *(float4*)&s_phif[c << 2] = *(const float4*)&g_phif[(size_t)eb * NRBF + (c << 2)];
        int t = c - 80;
        if (t >= 0 && t < cnt * 3)
            s_dir[t] = g_dir[(size_t)eb * 3 + t];
        if (c < cnt) s_fcut[c] = g_fcut[eb + c];
        int u = c - 16;
        if (u >= 0 && u < cnt) s_idx[u] = idx_j[eb + u];
        __syncthreads();

        for (int i = 0; i < cnt; i++) {
            int j = s_idx[i];
            float4 xv = *(const float4*)&x[(size_t)j * 512 + (c << 2)];
            const u64* pv = (const u64*)&s_phif[i * NRBF];
            u64 aq = 0ull, ar = 0ull;
#pragma unroll
            for (int r = 0; r < 10; r++) {
                u64 pr = pv[r];
                aq = ffma2(pr, WQ2[r], aq);
                ar = ffma2(pr, WR2[r], ar);
            }
            float fc = s_fcut[i];
            float2 fq = unpack2(aq), fr = unpack2(ar);
            float Wq = fmaf(fc, FBq, fq.x + fq.y);
            float Wr = fmaf(fc, FBr, fr.x + fr.y);

            float d0 = s_dir[i * 3 + 0], d1 = s_dir[i * 3 + 1], d2 = s_dir[i * 3 + 2];
            accq = fmaf(Wq, xv.x, accq);
            float tt = Wr * xv.y;
            am0 = fmaf(tt, d0, am0);
            am1 = fmaf(tt, d1, am1);
            am2 = fmaf(tt, d2, am2);
        }
    }
    q[(size_t)node * 128 + c] += accq;
    size_t mb = (size_t)node * 384;
    mu_out[mb + c]       = am0;
    mu_out[mb + 128 + c] = am1;
    mu_out[mb + 256 + c] = am2;
}

// ---------------- final per-node update (s computed inline) ----------------
// x2 is in the STANDARD [N][384] layout (written by the mixing-W2 gemm).
__global__ void epi2_kernel(float* __restrict__ q, float* __restrict__ mu, int N) {
    int t = blockIdx.x * blockDim.x + threadIdx.x;
    if (t >= N * 128) return;
    int n = t >> 7, c = t & 127;
    const float* xr = &g_x[(size_t)n * 384];
    float dq   = xr[c];
    float dmu  = xr[128 + c];
    float dqmu = xr[256 + c];
    const float* mm = &g_mumix[(size_t)n * 768];
    float v0 = mm[c],       v1 = mm[256 + c], v2 = mm[512 + c];
    float w0 = mm[128 + c], w1 = mm[384 + c], w2 = mm[640 + c];
    float s = v0 * w0 + v1 * w1 + v2 * w2;
    q[t] += dq + dqmu * s;
    size_t mb = (size_t)n * 384;
    mu[mb + c]       += dmu * w0;
    mu[mb + 128 + c] += dmu * w1;
    mu[mb + 256 + c] += dmu * w2;
}

// ---------------- host launch ----------------
extern "C" void kernel_launch(void* const* d_in, const int* in_sizes, int n_in,
                              void* d_out, int out_size) {
    const int*   an     = (const int*)  d_in[0];
    const float* r_ij   = (const float*)d_in[1];
    const int*   idx_i  = (const int*)  d_in[2];
    const int*   idx_j  = (const int*)  d_in[3];
    const float* emb    = (const float*)d_in[4];
    const float* filt_W = (const float*)d_in[5];
    const float* filt_b = (const float*)d_in[6];
    const float* int_W1 = (const float*)d_in[7];
    const float* int_b1 = (const float*)d_in[8];
    const float* int_W2 = (const float*)d_in[9];
    const float* int_b2 = (const float*)d_in[10];
    const float* mix_W1 = (const float*)d_in[11];
    const float* mix_b1 = (const float*)d_in[12];
    const float* mix_W2 = (const float*)d_in[13];
    const float* mix_b2 = (const float*)d_in[14];
    const float* mux_W  = (const float*)d_in[15];

    int N = in_sizes[0];
    int E = in_sizes[3];

    float* q      = (float*)d_out;          // [N,128]
    float* mu_out = q + (size_t)N * 128;    // [N,3,128]

    void* pA; cudaGetSymbolAddress(&pA, g_muA);  float* muA  = (float*)pA;
    void* pH; cudaGetSymbolAddress(&pH, g_h);    float* h    = (float*)pH;
    void* pX; cudaGetSymbolAddress(&pX, g_x);    float* xbuf = (float*)pX;
    void* pM; cudaGetSymbolAddress(&pM, g_mumix);float* mumix= (float*)pM;

    // fused setup: pre (E threads) + init (N*128) + rowptr (N+1)
    {
        int tot = N * 128 > E ? N * 128 : E;
        if (tot < N + 1) tot = N + 1;
        setup_kernel<<<(tot + 255) / 256, 256>>>(r_ij, idx_i, an, emb, q, E, N);
    }

    for (int l = 0; l < NLAYERS; l++) {
        float* mu_in = (l & 1) ? mu_out : muA;
        float* mu_o  = (l & 1) ? muA    : mu_out;

        // interaction: h = silu(q W1 + b1)
        {
            dim3 g(128 / 64, (N + 63) / 64);
            gemm64<1, 0><<<g, 256>>>(q, int_W1 + (size_t)l * 128 * 128,
                                     int_b1 + l * 128, h, N, 128, 128);
        }
        // x = h W2 + b2 -> interleaved [N][128][4] layout for the edge gather
        {
            dim3 g(384 / 64, (N + 63) / 64);
            gemm64<0, 1><<<g, 256>>>(h, int_W2 + (size_t)l * 128 * 384,
                                     int_b2 + l * 384, xbuf, N, 384, 128);
        }
        // edge messages + segment sum (one block per node)
        if (l == 0) {
            edge0_kernel<<<N, 128>>>(xbuf, q, mu_o, idx_j, filt_W, filt_b, N);
        } else {
            edge_kernel<<<N, 128>>>(xbuf, q, mu_in, mu_o, idx_j,
                                    filt_W, filt_b, l, N);
        }
        // mixing: mumix = mu @ mux_W (no bias), A viewed as [3N,128]
        {
            dim3 g(256 / 64, (3 * N + 63) / 64);
            gemm64<0, 0><<<g, 256>>>(mu_o, mux_W + (size_t)l * 128 * 256,
                                     nullptr, mumix, 3 * N, 256, 128);
        }
        // h = silu(ctx mix_W1 + b1), ctx built on the fly from q + mumix norms
        {
            dim3 g(128 / 64, (N + 63) / 64);
            gemm_ctx<<<g, 256>>>(q, mumix, mix_W1 + (size_t)l * 256 * 128,
                                 mix_b1 + l * 128, h, N);
        }
        // x2 = h mix_W2 + b2 (standard layout, read by epi2)
        {
            dim3 g(384 / 64, (N + 63) / 64);
            gemm64<0, 0><<<g, 256>>>(h, mix_W2 + (size_t)l * 128 * 384,
                                     mix_b2 + l * 384, xbuf, N, 384, 128);
        }
        epi2_kernel<<<((size_t)N * 128 + 255) / 256, 256>>>(q, mu_o, N);
    }
    // layer parity: l=0 in=(zero) out=d_out, l=1 in=d_out out=muA, l=2 in=muA out=d_out.
    // Final q and mu land in d_out. (q lives in d_out throughout.)
}

// round 15
// speedup vs baseline: 1.0557x; 1.0557x over previous
#include <cuda_runtime.h>
#include <math.h>

#define NRBF  20
#define MAXN  10000
#define MAXE  320000
#define NLAYERS 3
#define EB 32   // edge batch staged through smem (avg degree = 32 -> 1 batch/node)

typedef unsigned long long u64;

// ---------------- packed f32x2 helpers (sm_103a FFMA2) ----------------
__device__ __forceinline__ u64 ffma2(u64 a, u64 b, u64 c) {
    u64 d;
    asm("fma.rn.f32x2 %0, %1, %2, %3;" : "=l"(d) : "l"(a), "l"(b), "l"(c));
    return d;
}
__device__ __forceinline__ u64 pack2(float lo, float hi) {
    u64 d;
    asm("mov.b64 %0, {%1, %2};" : "=l"(d) : "f"(lo), "f"(hi));
    return d;
}
__device__ __forceinline__ float2 unpack2(u64 v) {
    float lo, hi;
    asm("mov.b64 {%0, %1}, %2;" : "=f"(lo), "=f"(hi) : "l"(v));
    return make_float2(lo, hi);
}

// ---------------- device scratch (allocation-free) ----------------
__device__ float g_dir  [MAXE * 3];
__device__ float g_phif [MAXE * NRBF];   // phi * fcut
__device__ float g_fcut [MAXE];
__device__ int   g_rowptr[MAXN + 1];
__device__ float g_x    [MAXN * 384];
__device__ float g_h    [MAXN * 128];
__device__ float g_muA  [MAXN * 384];
__device__ float g_mumix[MAXN * 768];    // [N,3,256]

// ---------------- fused setup: edge geometry/RBF + rowptr + q init ----------
__global__ void setup_kernel(const float* __restrict__ r_ij,
                             const int* __restrict__ idx_i,
                             const int* __restrict__ an,
                             const float* __restrict__ emb,
                             float* __restrict__ q,
                             int E, int N) {
    int t = blockIdx.x * blockDim.x + threadIdx.x;
    if (t < E) {
        int e = t;
        float x = r_ij[e * 3 + 0];
        float y = r_ij[e * 3 + 1];
        float z = r_ij[e * 3 + 2];
        float d = sqrtf(x * x + y * y + z * z);
        float inv = 1.0f / d;
        g_dir[e * 3 + 0] = x * inv;
        g_dir[e * 3 + 1] = y * inv;
        g_dir[e * 3 + 2] = z * inv;
        float fc = (d < 5.0f) ? 0.5f * (cosf(d * 0.62831853071795864769f) + 1.0f) : 0.0f;
        g_fcut[e] = fc;
        const float delta = 5.0f / 19.0f;
        const float coeff = -0.5f / (delta * delta);
#pragma unroll
        for (int r = 0; r < NRBF; r++) {
            float diff = d - delta * (float)r;
            g_phif[e * NRBF + r] = expf(coeff * diff * diff) * fc;
        }
    }
    if (t < N * 128) {
        int n = t >> 7, c = t & 127;
        q[t] = emb[an[n] * 128 + c];
    }
    if (t <= N) {
        int lo = 0, hi = E;
        while (lo < hi) {
            int mid = (lo + hi) >> 1;
            if (idx_i[mid] < t) lo = mid + 1; else hi = mid;
        }
        g_rowptr[t] = lo;
    }
}

// ---------------- double-buffered fp32 GEMM: C = act(A[M,K] @ W[K,N] + bias) --
// BM=BN=64, BK=32, 256 threads, 4x4 per thread. N % 64 == 0, K % 32 == 0.
template <int ACT>   // 0 = none, 1 = silu
__global__ void __launch_bounds__(256)
gemm64(const float* __restrict__ A, const float* __restrict__ W,
       const float* __restrict__ bias, float* __restrict__ C,
       int M, int N, int K) {
    __shared__ float As[2][32][68];
    __shared__ float Bs[2][32][68];
    const int tid  = threadIdx.x;
    const int row0 = blockIdx.y * 64;
    const int col0 = blockIdx.x * 64;
    const int tx = tid & 15, ty = tid >> 4;

    int ar0 = tid >> 3,          ak0 = (tid & 7) << 2;
    int ar1 = (tid + 256) >> 3;
    int br0 = tid >> 4,          bc0 = (tid & 15) << 2;
    int br1 = (tid + 256) >> 4;

    const bool av0 = (row0 + ar0) < M;
    const bool av1 = (row0 + ar1) < M;
    const float* Ap0 = A + (size_t)(row0 + ar0) * K + ak0;
    const float* Ap1 = A + (size_t)(row0 + ar1) * K + ak0;
    const float* Wp0 = W + (size_t)br0 * N + col0 + bc0;
    const float* Wp1 = W + (size_t)br1 * N + col0 + bc0;

    float4 a0 = av0 ? *(const float4*)Ap0 : make_float4(0.f, 0.f, 0.f, 0.f);
    float4 a1 = av1 ? *(const float4*)Ap1 : make_float4(0.f, 0.f, 0.f, 0.f);
    float4 b0 = *(const float4*)Wp0;
    float4 b1 = *(const float4*)Wp1;
    As[0][ak0 + 0][ar0] = a0.x; As[0][ak0 + 1][ar0] = a0.y;
    As[0][ak0 + 2][ar0] = a0.z; As[0][ak0 + 3][ar0] = a0.w;
    As[0][ak0 + 0][ar1] = a1.x; As[0][ak0 + 1][ar1] = a1.y;
    As[0][ak0 + 2][ar1] = a1.z; As[0][ak0 + 3][ar1] = a1.w;
    *(float4*)&Bs[0][br0][bc0] = b0;
    *(float4*)&Bs[0][br1][bc0] = b1;
    __syncthreads();

    float acc[4][4];
#pragma unroll
    for (int i = 0; i < 4; i++)
#pragma unroll
        for (int j = 0; j < 4; j++) acc[i][j] = 0.0f;

    int buf = 0;
    for (int k0 = 32; k0 < K; k0 += 32) {
        a0 = av0 ? *(const float4*)(Ap0 + k0) : make_float4(0.f, 0.f, 0.f, 0.f);
        a1 = av1 ? *(const float4*)(Ap1 + k0) : make_float4(0.f, 0.f, 0.f, 0.f);
        b0 = *(const float4*)(Wp0 + (size_t)k0 * N);
        b1 = *(const float4*)(Wp1 + (size_t)k0 * N);
#pragma unroll
        for (int kk = 0; kk < 32; kk++) {
            float4 a = *(const float4*)&As[buf][kk][ty << 2];
            float4 b = *(const float4*)&Bs[buf][kk][tx << 2];
            acc[0][0] = fmaf(a.x, b.x, acc[0][0]); acc[0][1] = fmaf(a.x, b.y, acc[0][1]);
            acc[0][2] = fmaf(a.x, b.z, acc[0][2]); acc[0][3] = fmaf(a.x, b.w, acc[0][3]);
            acc[1][0] = fmaf(a.y, b.x, acc[1][0]); acc[1][1] = fmaf(a.y, b.y, acc[1][1]);
            acc[1][2] = fmaf(a.y, b.z, acc[1][2]); acc[1][3] = fmaf(a.y, b.w, acc[1][3]);
            acc[2][0] = fmaf(a.z, b.x, acc[2][0]); acc[2][1] = fmaf(a.z, b.y, acc[2][1]);
            acc[2][2] = fmaf(a.z, b.z, acc[2][2]); acc[2][3] = fmaf(a.z, b.w, acc[2][3]);
            acc[3][0] = fmaf(a.w, b.x, acc[3][0]); acc[3][1] = fmaf(a.w, b.y, acc[3][1]);
            acc[3][2] = fmaf(a.w, b.z, acc[3][2]); acc[3][3] = fmaf(a.w, b.w, acc[3][3]);
        }
        buf ^= 1;
        As[buf][ak0 + 0][ar0] = a0.x; As[buf][ak0 + 1][ar0] = a0.y;
        As[buf][ak0 + 2][ar0] = a0.z; As[buf][ak0 + 3][ar0] = a0.w;
        As[buf][ak0 + 0][ar1] = a1.x; As[buf][ak0 + 1][ar1] = a1.y;
        As[buf][ak0 + 2][ar1] = a1.z; As[buf][ak0 + 3][ar1] = a1.w;
        *(float4*)&Bs[buf][br0][bc0] = b0;
        *(float4*)&Bs[buf][br1][bc0] = b1;
        __syncthreads();
    }
#pragma unroll
    for (int kk = 0; kk < 32; kk++) {
        float4 a = *(const float4*)&As[buf][kk][ty << 2];
        float4 b = *(const float4*)&Bs[buf][kk][tx << 2];
        acc[0][0] = fmaf(a.x, b.x, acc[0][0]); acc[0][1] = fmaf(a.x, b.y, acc[0][1]);
        acc[0][2] = fmaf(a.x, b.z, acc[0][2]); acc[0][3] = fmaf(a.x, b.w, acc[0][3]);
        acc[1][0] = fmaf(a.y, b.x, acc[1][0]); acc[1][1] = fmaf(a.y, b.y, acc[1][1]);
        acc[1][2] = fmaf(a.y, b.z, acc[1][2]); acc[1][3] = fmaf(a.y, b.w, acc[1][3]);
        acc[2][0] = fmaf(a.z, b.x, acc[2][0]); acc[2][1] = fmaf(a.z, b.y, acc[2][1]);
        acc[2][2] = fmaf(a.z, b.z, acc[2][2]); acc[2][3] = fmaf(a.z, b.w, acc[2][3]);
        acc[3][0] = fmaf(a.w, b.x, acc[3][0]); acc[3][1] = fmaf(a.w, b.y, acc[3][1]);
        acc[3][2] = fmaf(a.w, b.z, acc[3][2]); acc[3][3] = fmaf(a.w, b.w, acc[3][3]);
    }

    float bj[4] = {0.f, 0.f, 0.f, 0.f};
    if (bias) {
#pragma unroll
        for (int j = 0; j < 4; j++) bj[j] = bias[col0 + (tx << 2) + j];
    }
#pragma unroll
    for (int i = 0; i < 4; i++) {
        int r = row0 + (ty << 2) + i;
        if (r >= M) continue;
        float4 v;
        float* pv = &v.x;
#pragma unroll
        for (int j = 0; j < 4; j++) {
            float val = acc[i][j] + bj[j];
            if (ACT == 1) val = val / (1.0f + expf(-val));
            pv[j] = val;
        }
        *(float4*)&C[(size_t)r * N + col0 + (tx << 2)] = v;
    }
}

// ---------------- ctx A-operand builder -------------------------------------
__device__ __forceinline__ float4 ctx_load(const float* __restrict__ q,
                                           const float* __restrict__ mumix,
                                           int n, int k, bool valid) {
    if (!valid) return make_float4(0.f, 0.f, 0.f, 0.f);
    if (k < 128) return *(const float4*)&q[(size_t)n * 128 + k];
    int c = k - 128;
    const float* b = mumix + (size_t)n * 768;
    float4 v0 = *(const float4*)&b[c];
    float4 v1 = *(const float4*)&b[256 + c];
    float4 v2 = *(const float4*)&b[512 + c];
    float4 r;
    r.x = sqrtf(v0.x * v0.x + v1.x * v1.x + v2.x * v2.x + 1e-8f);
    r.y = sqrtf(v0.y * v0.y + v1.y * v1.y + v2.y * v2.y + 1e-8f);
    r.z = sqrtf(v0.z * v0.z + v1.z * v1.z + v2.z * v2.z + 1e-8f);
    r.w = sqrtf(v0.w * v0.w + v1.w * v1.w + v2.w * v2.w + 1e-8f);
    return r;
}

// ---------------- ctx GEMM: h = silu(ctx @ W + b), ctx built on the fly ------
__global__ void __launch_bounds__(256)
gemm_ctx(const float* __restrict__ q, const float* __restrict__ mumix,
         const float* __restrict__ W, const float* __restrict__ bias,
         float* __restrict__ C, int M) {
    const int Nn = 128, K = 256;
    __shared__ float As[2][32][68];
    __shared__ float Bs[2][32][68];
    const int tid  = threadIdx.x;
    const int row0 = blockIdx.y * 64;
    const int col0 = blockIdx.x * 64;
    const int tx = tid & 15, ty = tid >> 4;

    int ar0 = tid >> 3,          ak0 = (tid & 7) << 2;
    int ar1 = (tid + 256) >> 3;
    int br0 = tid >> 4,          bc0 = (tid & 15) << 2;
    int br1 = (tid + 256) >> 4;

    const bool av0 = (row0 + ar0) < M;
    const bool av1 = (row0 + ar1) < M;
    const float* Wp0 = W + (size_t)br0 * Nn + col0 + bc0;
    const float* Wp1 = W + (size_t)br1 * Nn + col0 + bc0;

    float4 a0 = ctx_load(q, mumix, row0 + ar0, ak0, av0);
    float4 a1 = ctx_load(q, mumix, row0 + ar1, ak0, av1);
    float4 b0 = *(const float4*)Wp0;
    float4 b1 = *(const float4*)Wp1;
    As[0][ak0 + 0][ar0] = a0.x; As[0][ak0 + 1][ar0] = a0.y;
    As[0][ak0 + 2][ar0] = a0.z; As[0][ak0 + 3][ar0] = a0.w;
    As[0][ak0 + 0][ar1] = a1.x; As[0][ak0 + 1][ar1] = a1.y;
    As[0][ak0 + 2][ar1] = a1.z; As[0][ak0 + 3][ar1] = a1.w;
    *(float4*)&Bs[0][br0][bc0] = b0;
    *(float4*)&Bs[0][br1][bc0] = b1;
    __syncthreads();

    float acc[4][4];
#pragma unroll
    for (int i = 0; i < 4; i++)
#pragma unroll
        for (int j = 0; j < 4; j++) acc[i][j] = 0.0f;

    int buf = 0;
    for (int k0 = 32; k0 < K; k0 += 32) {
        a0 = ctx_load(q, mumix, row0 + ar0, k0 + ak0, av0);
        a1 = ctx_load(q, mumix, row0 + ar1, k0 + ak0, av1);
        b0 = *(const float4*)(Wp0 + (size_t)k0 * Nn);
        b1 = *(const float4*)(Wp1 + (size_t)k0 * Nn);
#pragma unroll
        for (int kk = 0; kk < 32; kk++) {
            float4 a = *(const float4*)&As[buf][kk][ty << 2];
            float4 b = *(const float4*)&Bs[buf][kk][tx << 2];
            acc[0][0] = fmaf(a.x, b.x, acc[0][0]); acc[0][1] = fmaf(a.x, b.y, acc[0][1]);
            acc[0][2] = fmaf(a.x, b.z, acc[0][2]); acc[0][3] = fmaf(a.x, b.w, acc[0][3]);
            acc[1][0] = fmaf(a.y, b.x, acc[1][0]); acc[1][1] = fmaf(a.y, b.y, acc[1][1]);
            acc[1][2] = fmaf(a.y, b.z, acc[1][2]); acc[1][3] = fmaf(a.y, b.w, acc[1][3]);
            acc[2][0] = fmaf(a.z, b.x, acc[2][0]); acc[2][1] = fmaf(a.z, b.y, acc[2][1]);
            acc[2][2] = fmaf(a.z, b.z, acc[2][2]); acc[2][3] = fmaf(a.z, b.w, acc[2][3]);
            acc[3][0] = fmaf(a.w, b.x, acc[3][0]); acc[3][1] = fmaf(a.w, b.y, acc[3][1]);
            acc[3][2] = fmaf(a.w, b.z, acc[3][2]); acc[3][3] = fmaf(a.w, b.w, acc[3][3]);
        }
        buf ^= 1;
        As[buf][ak0 + 0][ar0] = a0.x; As[buf][ak0 + 1][ar0] = a0.y;
        As[buf][ak0 + 2][ar0] = a0.z; As[buf][ak0 + 3][ar0] = a0.w;
        As[buf][ak0 + 0][ar1] = a1.x; As[buf][ak0 + 1][ar1] = a1.y;
        As[buf][ak0 + 2][ar1] = a1.z; As[buf][ak0 + 3][ar1] = a1.w;
        *(float4*)&Bs[buf][br0][bc0] = b0;
        *(float4*)&Bs[buf][br1][bc0] = b1;
        __syncthreads();
    }
#pragma unroll
    for (int kk = 0; kk < 32; kk++) {
        float4 a = *(const float4*)&As[buf][kk][ty << 2];
        float4 b = *(const float4*)&Bs[buf][kk][tx << 2];
        acc[0][0] = fmaf(a.x, b.x, acc[0][0]); acc[0][1] = fmaf(a.x, b.y, acc[0][1]);
        acc[0][2] = fmaf(a.x, b.z, acc[0][2]); acc[0][3] = fmaf(a.x, b.w, acc[0][3]);
        acc[1][0] = fmaf(a.y, b.x, acc[1][0]); acc[1][1] = fmaf(a.y, b.y, acc[1][1]);
        acc[1][2] = fmaf(a.y, b.z, acc[1][2]); acc[1][3] = fmaf(a.y, b.w, acc[1][3]);
        acc[2][0] = fmaf(a.z, b.x, acc[2][0]); acc[2][1] = fmaf(a.z, b.y, acc[2][1]);
        acc[2][2] = fmaf(a.z, b.z, acc[2][2]); acc[2][3] = fmaf(a.z, b.w, acc[2][3]);
        acc[3][0] = fmaf(a.w, b.x, acc[3][0]); acc[3][1] = fmaf(a.w, b.y, acc[3][1]);
        acc[3][2] = fmaf(a.w, b.z, acc[3][2]); acc[3][3] = fmaf(a.w, b.w, acc[3][3]);
    }

    float bj[4];
#pragma unroll
    for (int j = 0; j < 4; j++) bj[j] = bias[col0 + (tx << 2) + j];
#pragma unroll
    for (int i = 0; i < 4; i++) {
        int r = row0 + (ty << 2) + i;
        if (r >= M) continue;
        float4 v;
        float* pv = &v.x;
#pragma unroll
        for (int j = 0; j < 4; j++) {
            float val = acc[i][j] + bj[j];
            val = val / (1.0f + expf(-val));
            pv[j] = val;
        }
        *(float4*)&C[(size_t)r * Nn + col0 + (tx << 2)] = v;
    }
}

// ---------------- edge message + segment-sum kernel (general layers) --------
// ROUND-11 PROVEN pipeline (staged pp[10]); EB=32: one staging batch covers
// the average node degree, halving barriers + staging round-trips.
__global__ void __launch_bounds__(128)
edge_kernel(const float* __restrict__ x,
            float* __restrict__ q,
            const float* __restrict__ mu_in,
            float* __restrict__ mu_out,
            const int* __restrict__ idx_j,
            const float* __restrict__ filt_W,
            const float* __restrict__ filt_b,
            int layer, int N) {
    __shared__ __align__(16) float s_phif[EB * NRBF];
    __shared__ float s_dir[EB * 3];
    __shared__ float s_fcut[EB];
    __shared__ int   s_idx[EB];

    int c = threadIdx.x;   // 0..127
    int layOff = layer * 384;
    u64 WQ2[10], WR2[10], WM2[10];
#pragma unroll
    for (int r2 = 0; r2 < 10; r2++) {
        const float* f0 = &filt_W[(2 * r2)     * (NLAYERS * 384) + layOff];
        const float* f1 = &filt_W[(2 * r2 + 1) * (NLAYERS * 384) + layOff];
        WQ2[r2] = pack2(f0[c],       f1[c]);
        WR2[r2] = pack2(f0[128 + c], f1[128 + c]);
        WM2[r2] = pack2(f0[256 + c], f1[256 + c]);
    }
    float FBq = filt_b[layOff + c];
    float FBr = filt_b[layOff + 128 + c];
    float FBm = filt_b[layOff + 256 + c];

    int node = blockIdx.x;
    if (node >= N) return;
    int e0 = g_rowptr[node], e1 = g_rowptr[node + 1];
    float accq = 0.f, am0 = 0.f, am1 = 0.f, am2 = 0.f;

    for (int eb = e0; eb < e1; eb += EB) {
        int cnt = min(EB, e1 - eb);
        __syncthreads();
        for (int s = c; s < cnt * 5; s += 128)
            *(float4*)&s_phif[s << 2] = *(const float4*)&g_phif[(size_t)eb * NRBF + (s << 2)];
        if (c < cnt * 3) s_dir[c] = g_dir[(size_t)eb * 3 + c];
        if (c < cnt) { s_fcut[c] = g_fcut[eb + c]; s_idx[c] = idx_j[eb + c]; }
        __syncthreads();

        for (int i = 0; i < cnt; i++) {
            int j = s_idx[i];
            const float* xr = &x[(size_t)j * 384];
            const float* mj = &mu_in[(size_t)j * 384];
            float xq = xr[c], xR = xr[128 + c], xM = xr[256 + c];
            float m0 = mj[c], m1 = mj[128 + c], m2 = mj[256 + c];
            u64 pp[10];
            const ulonglong2* pv = (const ulonglong2*)&s_phif[i * NRBF];
#pragma unroll
            for (int v = 0; v < 5; v++) {
                ulonglong2 tt2 = pv[v];
                pp[2 * v]     = tt2.x;
                pp[2 * v + 1] = tt2.y;
            }
            u64 aq = 0ull, ar = 0ull, am = 0ull;
#pragma unroll
            for (int r = 0; r < 10; r++) {
                aq = ffma2(pp[r], WQ2[r], aq);
                ar = ffma2(pp[r], WR2[r], ar);
                am = ffma2(pp[r], WM2[r], am);
            }
            float fc = s_fcut[i];
            float2 fq = unpack2(aq), fr = unpack2(ar), fm = unpack2(am);
            float Wq = fmaf(fc, FBq, fq.x + fq.y);
            float Wr = fmaf(fc, FBr, fr.x + fr.y);
            float Wm = fmaf(fc, FBm, fm.x + fm.y);

            float d0 = s_dir[i * 3 + 0], d1 = s_dir[i * 3 + 1], d2 = s_dir[i * 3 + 2];
            accq = fmaf(Wq, xq, accq);
            float tt  = Wr * xR;
            float wmx = Wm * xM;
            am0 = fmaf(tt, d0, fmaf(wmx, m0, am0));
            am1 = fmaf(tt, d1, fmaf(wmx, m1, am1));
            am2 = fmaf(tt, d2, fmaf(wmx, m2, am2));
        }
    }
    q[(size_t)node * 128 + c] += accq;
    size_t mb = (size_t)node * 384;
    mu_out[mb + c]       = mu_in[mb + c]       + am0;
    mu_out[mb + 128 + c] = mu_in[mb + 128 + c] + am1;
    mu_out[mb + 256 + c] = mu_in[mb + 256 + c] + am2;
}

// ---------------- layer-0 edge kernel: mu_in == 0 everywhere ----------------
// ROUND-12 PROVEN inline-LDS variant with EB=32 staging.
__global__ void __launch_bounds__(128)
edge0_kernel(const float* __restrict__ x,
             float* __restrict__ q,
             float* __restrict__ mu_out,
             const int* __restrict__ idx_j,
             const float* __restrict__ filt_W,
             const float* __restrict__ filt_b,
             int N) {
    __shared__ __align__(16) float s_phif[EB * NRBF];
    __shared__ float s_dir[EB * 3];
    __shared__ float s_fcut[EB];
    __shared__ int   s_idx[EB];

    int c = threadIdx.x;
    u64 WQ2[10], WR2[10];
#pragma unroll
    for (int r2 = 0; r2 < 10; r2++) {
        const float* f0 = &filt_W[(2 * r2)     * (NLAYERS * 384)];
        const float* f1 = &filt_W[(2 * r2 + 1) * (NLAYERS * 384)];
        WQ2[r2] = pack2(f0[c],       f1[c]);
        WR2[r2] = pack2(f0[128 + c], f1[128 + c]);
    }
    float FBq = filt_b[c];
    float FBr = filt_b[128 + c];

    int node = blockIdx.x;
    if (node >= N) return;
    int e0 = g_rowptr[node], e1 = g_rowptr[node + 1];
    float accq = 0.f, am0 = 0.f, am1 = 0.f, am2 = 0.f;

    for (int eb = e0; eb < e1; eb += EB) {
        int cnt = min(EB, e1 - eb);
        __syncthreads();
        for (int s = c; s < cnt * 5; s += 128)
            *(float4*)&s_phif[s << 2] = *(const float4*)&g_phif[(size_t)eb * NRBF + (s << 2)];
        if (c < cnt * 3) s_dir[c] = g_dir[(size_t)eb * 3 + c];
        if (c < cnt) { s_fcut[c] = g_fcut[eb + c]; s_idx[c] = idx_j[eb + c]; }
        __syncthreads();

        for (int i = 0; i < cnt; i++) {
            int j = s_idx[i];
            const float* xr = &x[(size_t)j * 384];
            float xq = xr[c], xR = xr[128 + c];
            const u64* pv = (const u64*)&s_phif[i * NRBF];
            u64 aq = 0ull, ar = 0ull;
#pragma unroll
            for (int r = 0; r < 10; r++) {
                u64 pr = pv[r];
                aq = ffma2(pr, WQ2[r], aq);
                ar = ffma2(pr, WR2[r], ar);
            }
            float fc = s_fcut[i];
            float2 fq = unpack2(aq), fr = unpack2(ar);
            float Wq = fmaf(fc, FBq, fq.x + fq.y);
            float Wr = fmaf(fc, FBr, fr.x + fr.y);

            float d0 = s_dir[i * 3 + 0], d1 = s_dir[i * 3 + 1], d2 = s_dir[i * 3 + 2];
            accq = fmaf(Wq, xq, accq);
            float tt = Wr * xR;
            am0 = fmaf(tt, d0, am0);
            am1 = fmaf(tt, d1, am1);
            am2 = fmaf(tt, d2, am2);
        }
    }
    q[(size_t)node * 128 + c] += accq;
    size_t mb = (size_t)node * 384;
    mu_out[mb + c]       = am0;
    mu_out[mb + 128 + c] = am1;
    mu_out[mb + 256 + c] = am2;
}

// ---------------- final per-node update (s computed inline) ----------------
__global__ void epi2_kernel(float* __restrict__ q, float* __restrict__ mu, int N) {
    int t = blockIdx.x * blockDim.x + threadIdx.x;
    if (t >= N * 128) return;
    int n = t >> 7, c = t & 127;
    const float* xr = &g_x[(size_t)n * 384];
    float dq   = xr[c];
    float dmu  = xr[128 + c];
    float dqmu = xr[256 + c];
    const float* mm = &g_mumix[(size_t)n * 768];
    float v0 = mm[c],       v1 = mm[256 + c], v2 = mm[512 + c];
    float w0 = mm[128 + c], w1 = mm[384 + c], w2 = mm[640 + c];
    float s = v0 * w0 + v1 * w1 + v2 * w2;
    q[t] += dq + dqmu * s;
    size_t mb = (size_t)n * 384;
    mu[mb + c]       += dmu * w0;
    mu[mb + 128 + c] += dmu * w1;
    mu[mb + 256 + c] += dmu * w2;
}

// ---------------- host launch ----------------
extern "C" void kernel_launch(void* const* d_in, const int* in_sizes, int n_in,
                              void* d_out, int out_size) {
    const int*   an     = (const int*)  d_in[0];
    const float* r_ij   = (const float*)d_in[1];
    const int*   idx_i  = (const int*)  d_in[2];
    const int*   idx_j  = (const int*)  d_in[3];
    const float* emb    = (const float*)d_in[4];
    const float* filt_W = (const float*)d_in[5];
    const float* filt_b = (const float*)d_in[6];
    const float* int_W1 = (const float*)d_in[7];
    const float* int_b1 = (const float*)d_in[8];
    const float* int_W2 = (const float*)d_in[9];
    const float* int_b2 = (const float*)d_in[10];
    const float* mix_W1 = (const float*)d_in[11];
    const float* mix_b1 = (const float*)d_in[12];
    const float* mix_W2 = (const float*)d_in[13];
    const float* mix_b2 = (const float*)d_in[14];
    const float* mux_W  = (const float*)d_in[15];

    int N = in_sizes[0];
    int E = in_sizes[3];

    float* q      = (float*)d_out;          // [N,128]
    float* mu_out = q + (size_t)N * 128;    // [N,3,128]

    void* pA; cudaGetSymbolAddress(&pA, g_muA);  float* muA  = (float*)pA;
    void* pH; cudaGetSymbolAddress(&pH, g_h);    float* h    = (float*)pH;
    void* pX; cudaGetSymbolAddress(&pX, g_x);    float* xbuf = (float*)pX;
    void* pM; cudaGetSymbolAddress(&pM, g_mumix);float* mumix= (float*)pM;

    // fused setup: pre (E threads) + init (N*128) + rowptr (N+1)
    {
        int tot = N * 128 > E ? N * 128 : E;
        if (tot < N + 1) tot = N + 1;
        setup_kernel<<<(tot + 255) / 256, 256>>>(r_ij, idx_i, an, emb, q, E, N);
    }

    for (int l = 0; l < NLAYERS; l++) {
        float* mu_in = (l & 1) ? mu_out : muA;
        float* mu_o  = (l & 1) ? muA    : mu_out;

        // interaction: h = silu(q W1 + b1)
        {
            dim3 g(128 / 64, (N + 63) / 64);
            gemm64<1><<<g, 256>>>(q, int_W1 + (size_t)l * 128 * 128,
                                  int_b1 + l * 128, h, N, 128, 128);
        }
        // x = h W2 + b2
        {
            dim3 g(384 / 64, (N + 63) / 64);
            gemm64<0><<<g, 256>>>(h, int_W2 + (size_t)l * 128 * 384,
                                  int_b2 + l * 384, xbuf, N, 384, 128);
        }
        // edge messages + segment sum (one block per node)
        if (l == 0) {
            edge0_kernel<<<N, 128>>>(xbuf, q, mu_o, idx_j, filt_W, filt_b, N);
        } else {
            edge_kernel<<<N, 128>>>(xbuf, q, mu_in, mu_o, idx_j,
                                    filt_W, filt_b, l, N);
        }
        // mixing: mumix = mu @ mux_W (no bias), A viewed as [3N,128]
        {
            dim3 g(256 / 64, (3 * N + 63) / 64);
            gemm64<0><<<g, 256>>>(mu_o, mux_W + (size_t)l * 128 * 256,
                                  nullptr, mumix, 3 * N, 256, 128);
        }
        // h = silu(ctx mix_W1 + b1), ctx built on the fly from q + mumix norms
        {
            dim3 g(128 / 64, (N + 63) / 64);
            gemm_ctx<<<g, 256>>>(q, mumix, mix_W1 + (size_t)l * 256 * 128,
                                 mix_b1 + l * 128, h, N);
        }
        // x2 = h mix_W2 + b2 (into xbuf)
        {
            dim3 g(384 / 64, (N + 63) / 64);
            gemm64<0><<<g, 256>>>(h, mix_W2 + (size_t)l * 128 * 384,
                                  mix_b2 + l * 384, xbuf, N, 384, 128);
        }
        epi2_kernel<<<((size_t)N * 128 + 255) / 256, 256>>>(q, mu_o, N);
    }
    // layer parity: l=0 in=(zero) out=d_out, l=1 in=d_out out=muA, l=2 in=muA out=d_out.
    // Final q and mu land in d_out. (q lives in d_out throughout.)
}

// round 16
// speedup vs baseline: 1.0814x; 1.0244x over previous
#include <cuda_runtime.h>
#include <math.h>

#define NRBF  20
#define MAXN  10000
#define MAXE  320000
#define NLAYERS 3
#define EB 32   // edge batch staged through smem (avg degree = 32 -> 1 batch/node)

typedef unsigned long long u64;

// ---------------- packed f32x2 helpers (sm_103a FFMA2) ----------------
__device__ __forceinline__ u64 ffma2(u64 a, u64 b, u64 c) {
    u64 d;
    asm("fma.rn.f32x2 %0, %1, %2, %3;" : "=l"(d) : "l"(a), "l"(b), "l"(c));
    return d;
}
__device__ __forceinline__ u64 pack2(float lo, float hi) {
    u64 d;
    asm("mov.b64 %0, {%1, %2};" : "=l"(d) : "f"(lo), "f"(hi));
    return d;
}
__device__ __forceinline__ float2 unpack2(u64 v) {
    float lo, hi;
    asm("mov.b64 {%0, %1}, %2;" : "=f"(lo), "=f"(hi) : "l"(v));
    return make_float2(lo, hi);
}

// ---------------- device scratch (allocation-free) ----------------
__device__ float g_dir  [MAXE * 3];
__device__ float g_phif [MAXE * NRBF];   // phi * fcut
__device__ float g_fcut [MAXE];
__device__ int   g_rowptr[MAXN + 1];
__device__ float g_x    [MAXN * 384];
__device__ float g_h    [MAXN * 128];
__device__ float g_muA  [MAXN * 384];
__device__ float g_mumix[MAXN * 768];    // [N,3,256]

// ---------------- fused setup: edge geometry/RBF + rowptr + q init ----------
__global__ void setup_kernel(const float* __restrict__ r_ij,
                             const int* __restrict__ idx_i,
                             const int* __restrict__ an,
                             const float* __restrict__ emb,
                             float* __restrict__ q,
                             int E, int N) {
    int t = blockIdx.x * blockDim.x + threadIdx.x;
    if (t < E) {
        int e = t;
        float x = r_ij[e * 3 + 0];
        float y = r_ij[e * 3 + 1];
        float z = r_ij[e * 3 + 2];
        float d = sqrtf(x * x + y * y + z * z);
        float inv = 1.0f / d;
        g_dir[e * 3 + 0] = x * inv;
        g_dir[e * 3 + 1] = y * inv;
        g_dir[e * 3 + 2] = z * inv;
        float fc = (d < 5.0f) ? 0.5f * (cosf(d * 0.62831853071795864769f) + 1.0f) : 0.0f;
        g_fcut[e] = fc;
        const float delta = 5.0f / 19.0f;
        const float coeff = -0.5f / (delta * delta);
#pragma unroll
        for (int r = 0; r < NRBF; r++) {
            float diff = d - delta * (float)r;
            g_phif[e * NRBF + r] = expf(coeff * diff * diff) * fc;
        }
    }
    if (t < N * 128) {
        int n = t >> 7, c = t & 127;
        q[t] = emb[an[n] * 128 + c];
    }
    if (t <= N) {
        int lo = 0, hi = E;
        while (lo < hi) {
            int mid = (lo + hi) >> 1;
            if (idx_i[mid] < t) lo = mid + 1; else hi = mid;
        }
        g_rowptr[t] = lo;
    }
}

// ---------------- double-buffered fp32 GEMM: C = act(A[M,K] @ W[K,N] + bias) --
// BM=BN=64, BK=32, 256 threads, 4x4 per thread. Used for small-M/N launches.
template <int ACT>   // 0 = none, 1 = silu
__global__ void __launch_bounds__(256)
gemm64(const float* __restrict__ A, const float* __restrict__ W,
       const float* __restrict__ bias, float* __restrict__ C,
       int M, int N, int K) {
    __shared__ float As[2][32][68];
    __shared__ float Bs[2][32][68];
    const int tid  = threadIdx.x;
    const int row0 = blockIdx.y * 64;
    const int col0 = blockIdx.x * 64;
    const int tx = tid & 15, ty = tid >> 4;

    int ar0 = tid >> 3,          ak0 = (tid & 7) << 2;
    int ar1 = (tid + 256) >> 3;
    int br0 = tid >> 4,          bc0 = (tid & 15) << 2;
    int br1 = (tid + 256) >> 4;

    const bool av0 = (row0 + ar0) < M;
    const bool av1 = (row0 + ar1) < M;
    const float* Ap0 = A + (size_t)(row0 + ar0) * K + ak0;
    const float* Ap1 = A + (size_t)(row0 + ar1) * K + ak0;
    const float* Wp0 = W + (size_t)br0 * N + col0 + bc0;
    const float* Wp1 = W + (size_t)br1 * N + col0 + bc0;

    float4 a0 = av0 ? *(const float4*)Ap0 : make_float4(0.f, 0.f, 0.f, 0.f);
    float4 a1 = av1 ? *(const float4*)Ap1 : make_float4(0.f, 0.f, 0.f, 0.f);
    float4 b0 = *(const float4*)Wp0;
    float4 b1 = *(const float4*)Wp1;
    As[0][ak0 + 0][ar0] = a0.x; As[0][ak0 + 1][ar0] = a0.y;
    As[0][ak0 + 2][ar0] = a0.z; As[0][ak0 + 3][ar0] = a0.w;
    As[0][ak0 + 0][ar1] = a1.x; As[0][ak0 + 1][ar1] = a1.y;
    As[0][ak0 + 2][ar1] = a1.z; As[0][ak0 + 3][ar1] = a1.w;
    *(float4*)&Bs[0][br0][bc0] = b0;
    *(float4*)&Bs[0][br1][bc0] = b1;
    __syncthreads();

    float acc[4][4];
#pragma unroll
    for (int i = 0; i < 4; i++)
#pragma unroll
        for (int j = 0; j < 4; j++) acc[i][j] = 0.0f;

    int buf = 0;
    for (int k0 = 32; k0 < K; k0 += 32) {
        a0 = av0 ? *(const float4*)(Ap0 + k0) : make_float4(0.f, 0.f, 0.f, 0.f);
        a1 = av1 ? *(const float4*)(Ap1 + k0) : make_float4(0.f, 0.f, 0.f, 0.f);
        b0 = *(const float4*)(Wp0 + (size_t)k0 * N);
        b1 = *(const float4*)(Wp1 + (size_t)k0 * N);
#pragma unroll
        for (int kk = 0; kk < 32; kk++) {
            float4 a = *(const float4*)&As[buf][kk][ty << 2];
            float4 b = *(const float4*)&Bs[buf][kk][tx << 2];
            acc[0][0] = fmaf(a.x, b.x, acc[0][0]); acc[0][1] = fmaf(a.x, b.y, acc[0][1]);
            acc[0][2] = fmaf(a.x, b.z, acc[0][2]); acc[0][3] = fmaf(a.x, b.w, acc[0][3]);
            acc[1][0] = fmaf(a.y, b.x, acc[1][0]); acc[1][1] = fmaf(a.y, b.y, acc[1][1]);
            acc[1][2] = fmaf(a.y, b.z, acc[1][2]); acc[1][3] = fmaf(a.y, b.w, acc[1][3]);
            acc[2][0] = fmaf(a.z, b.x, acc[2][0]); acc[2][1] = fmaf(a.z, b.y, acc[2][1]);
            acc[2][2] = fmaf(a.z, b.z, acc[2][2]); acc[2][3] = fmaf(a.z, b.w, acc[2][3]);
            acc[3][0] = fmaf(a.w, b.x, acc[3][0]); acc[3][1] = fmaf(a.w, b.y, acc[3][1]);
            acc[3][2] = fmaf(a.w, b.z, acc[3][2]); acc[3][3] = fmaf(a.w, b.w, acc[3][3]);
        }
        buf ^= 1;
        As[buf][ak0 + 0][ar0] = a0.x; As[buf][ak0 + 1][ar0] = a0.y;
        As[buf][ak0 + 2][ar0] = a0.z; As[buf][ak0 + 3][ar0] = a0.w;
        As[buf][ak0 + 0][ar1] = a1.x; As[buf][ak0 + 1][ar1] = a1.y;
        As[buf][ak0 + 2][ar1] = a1.z; As[buf][ak0 + 3][ar1] = a1.w;
        *(float4*)&Bs[buf][br0][bc0] = b0;
        *(float4*)&Bs[buf][br1][bc0] = b1;
        __syncthreads();
    }
#pragma unroll
    for (int kk = 0; kk < 32; kk++) {
        float4 a = *(const float4*)&As[buf][kk][ty << 2];
        float4 b = *(const float4*)&Bs[buf][kk][tx << 2];
        acc[0][0] = fmaf(a.x, b.x, acc[0][0]); acc[0][1] = fmaf(a.x, b.y, acc[0][1]);
        acc[0][2] = fmaf(a.x, b.z, acc[0][2]); acc[0][3] = fmaf(a.x, b.w, acc[0][3]);
        acc[1][0] = fmaf(a.y, b.x, acc[1][0]); acc[1][1] = fmaf(a.y, b.y, acc[1][1]);
        acc[1][2] = fmaf(a.y, b.z, acc[1][2]); acc[1][3] = fmaf(a.y, b.w, acc[1][3]);
        acc[2][0] = fmaf(a.z, b.x, acc[2][0]); acc[2][1] = fmaf(a.z, b.y, acc[2][1]);
        acc[2][2] = fmaf(a.z, b.z, acc[2][2]); acc[2][3] = fmaf(a.z, b.w, acc[2][3]);
        acc[3][0] = fmaf(a.w, b.x, acc[3][0]); acc[3][1] = fmaf(a.w, b.y, acc[3][1]);
        acc[3][2] = fmaf(a.w, b.z, acc[3][2]); acc[3][3] = fmaf(a.w, b.w, acc[3][3]);
    }

    float bj[4] = {0.f, 0.f, 0.f, 0.f};
    if (bias) {
#pragma unroll
        for (int j = 0; j < 4; j++) bj[j] = bias[col0 + (tx << 2) + j];
    }
#pragma unroll
    for (int i = 0; i < 4; i++) {
        int r = row0 + (ty << 2) + i;
        if (r >= M) continue;
        float4 v;
        float* pv = &v.x;
#pragma unroll
        for (int j = 0; j < 4; j++) {
            float val = acc[i][j] + bj[j];
            if (ACT == 1) val = val / (1.0f + expf(-val));
            pv[j] = val;
        }
        *(float4*)&C[(size_t)r * N + col0 + (tx << 2)] = v;
    }
}

// ---------------- big-M GEMM: BM=128, BN=64, BK=32, 8x4 per thread ----------
// Dynamic smem: As[2][32][132] + Bs[2][32][68] = 51200 B.
#define G128_AS(buf, k, m) Asm[(buf) * (32 * 132) + (k) * 132 + (m)]
#define G128_BS(buf, k, n) Bsm[(buf) * (32 * 68) + (k) * 68 + (n)]
#define G128_SMEM (2 * 32 * 132 + 2 * 32 * 68)

template <int ACT>
__global__ void __launch_bounds__(256)
gemm128(const float* __restrict__ A, const float* __restrict__ W,
        const float* __restrict__ bias, float* __restrict__ C,
        int M, int N, int K) {
    extern __shared__ float dsm[];
    float* Asm = dsm;
    float* Bsm = dsm + 2 * 32 * 132;
    const int tid  = threadIdx.x;
    const int row0 = blockIdx.y * 128;
    const int col0 = blockIdx.x * 64;
    const int tx = tid & 15, ty = tid >> 4;

    const int ak0 = (tid & 7) << 2;
    const int bc0 = (tid & 15) << 2;
    int arr0 = tid >> 3;                 // rows for A slots (s = tid + i*256 -> +32 per i)
    int brr0 = tid >> 4;                 // k-rows for B slots (+16 per i)

    bool av[4];
    const float* Ap[4];
#pragma unroll
    for (int i = 0; i < 4; i++) {
        int ar = arr0 + i * 32;
        av[i] = (row0 + ar) < M;
        Ap[i] = A + (size_t)(row0 + ar) * K + ak0;
    }
    const float* Wp0 = W + (size_t)brr0 * N + col0 + bc0;
    const float* Wp1 = W + (size_t)(brr0 + 16) * N + col0 + bc0;

    float4 aR[4], bR0, bR1;
#pragma unroll
    for (int i = 0; i < 4; i++)
        aR[i] = av[i] ? *(const float4*)Ap[i] : make_float4(0.f, 0.f, 0.f, 0.f);
    bR0 = *(const float4*)Wp0;
    bR1 = *(const float4*)Wp1;
#pragma unroll
    for (int i = 0; i < 4; i++) {
        int ar = arr0 + i * 32;
        G128_AS(0, ak0 + 0, ar) = aR[i].x; G128_AS(0, ak0 + 1, ar) = aR[i].y;
        G128_AS(0, ak0 + 2, ar) = aR[i].z; G128_AS(0, ak0 + 3, ar) = aR[i].w;
    }
    *(float4*)&G128_BS(0, brr0, bc0)      = bR0;
    *(float4*)&G128_BS(0, brr0 + 16, bc0) = bR1;
    __syncthreads();

    float acc[8][4];
#pragma unroll
    for (int i = 0; i < 8; i++)
#pragma unroll
        for (int j = 0; j < 4; j++) acc[i][j] = 0.0f;

    int buf = 0;
    for (int k0 = 32; k0 < K; k0 += 32) {
#pragma unroll
        for (int i = 0; i < 4; i++)
            aR[i] = av[i] ? *(const float4*)(Ap[i] + k0) : make_float4(0.f, 0.f, 0.f, 0.f);
        bR0 = *(const float4*)(Wp0 + (size_t)k0 * N);
        bR1 = *(const float4*)(Wp1 + (size_t)k0 * N);
#pragma unroll
        for (int kk = 0; kk < 32; kk++) {
            float4 a0 = *(const float4*)&G128_AS(buf, kk, ty << 3);
            float4 a1 = *(const float4*)&G128_AS(buf, kk, (ty << 3) + 4);
            float4 b  = *(const float4*)&G128_BS(buf, kk, tx << 2);
            acc[0][0] = fmaf(a0.x, b.x, acc[0][0]); acc[0][1] = fmaf(a0.x, b.y, acc[0][1]);
            acc[0][2] = fmaf(a0.x, b.z, acc[0][2]); acc[0][3] = fmaf(a0.x, b.w, acc[0][3]);
            acc[1][0] = fmaf(a0.y, b.x, acc[1][0]); acc[1][1] = fmaf(a0.y, b.y, acc[1][1]);
            acc[1][2] = fmaf(a0.y, b.z, acc[1][2]); acc[1][3] = fmaf(a0.y, b.w, acc[1][3]);
            acc[2][0] = fmaf(a0.z, b.x, acc[2][0]); acc[2][1] = fmaf(a0.z, b.y, acc[2][1]);
            acc[2][2] = fmaf(a0.z, b.z, acc[2][2]); acc[2][3] = fmaf(a0.z, b.w, acc[2][3]);
            acc[3][0] = fmaf(a0.w, b.x, acc[3][0]); acc[3][1] = fmaf(a0.w, b.y, acc[3][1]);
            acc[3][2] = fmaf(a0.w, b.z, acc[3][2]); acc[3][3] = fmaf(a0.w, b.w, acc[3][3]);
            acc[4][0] = fmaf(a1.x, b.x, acc[4][0]); acc[4][1] = fmaf(a1.x, b.y, acc[4][1]);
            acc[4][2] = fmaf(a1.x, b.z, acc[4][2]); acc[4][3] = fmaf(a1.x, b.w, acc[4][3]);
            acc[5][0] = fmaf(a1.y, b.x, acc[5][0]); acc[5][1] = fmaf(a1.y, b.y, acc[5][1]);
            acc[5][2] = fmaf(a1.y, b.z, acc[5][2]); acc[5][3] = fmaf(a1.y, b.w, acc[5][3]);
            acc[6][0] = fmaf(a1.z, b.x, acc[6][0]); acc[6][1] = fmaf(a1.z, b.y, acc[6][1]);
            acc[6][2] = fmaf(a1.z, b.z, acc[6][2]); acc[6][3] = fmaf(a1.z, b.w, acc[6][3]);
            acc[7][0] = fmaf(a1.w, b.x, acc[7][0]); acc[7][1] = fmaf(a1.w, b.y, acc[7][1]);
            acc[7][2] = fmaf(a1.w, b.z, acc[7][2]); acc[7][3] = fmaf(a1.w, b.w, acc[7][3]);
        }
        buf ^= 1;
#pragma unroll
        for (int i = 0; i < 4; i++) {
            int ar = arr0 + i * 32;
            G128_AS(buf, ak0 + 0, ar) = aR[i].x; G128_AS(buf, ak0 + 1, ar) = aR[i].y;
            G128_AS(buf, ak0 + 2, ar) = aR[i].z; G128_AS(buf, ak0 + 3, ar) = aR[i].w;
        }
        *(float4*)&G128_BS(buf, brr0, bc0)      = bR0;
        *(float4*)&G128_BS(buf, brr0 + 16, bc0) = bR1;
        __syncthreads();
    }
#pragma unroll
    for (int kk = 0; kk < 32; kk++) {
        float4 a0 = *(const float4*)&G128_AS(buf, kk, ty << 3);
        float4 a1 = *(const float4*)&G128_AS(buf, kk, (ty << 3) + 4);
        float4 b  = *(const float4*)&G128_BS(buf, kk, tx << 2);
        acc[0][0] = fmaf(a0.x, b.x, acc[0][0]); acc[0][1] = fmaf(a0.x, b.y, acc[0][1]);
        acc[0][2] = fmaf(a0.x, b.z, acc[0][2]); acc[0][3] = fmaf(a0.x, b.w, acc[0][3]);
        acc[1][0] = fmaf(a0.y, b.x, acc[1][0]); acc[1][1] = fmaf(a0.y, b.y, acc[1][1]);
        acc[1][2] = fmaf(a0.y, b.z, acc[1][2]); acc[1][3] = fmaf(a0.y, b.w, acc[1][3]);
        acc[2][0] = fmaf(a0.z, b.x, acc[2][0]); acc[2][1] = fmaf(a0.z, b.y, acc[2][1]);
        acc[2][2] = fmaf(a0.z, b.z, acc[2][2]); acc[2][3] = fmaf(a0.z, b.w, acc[2][3]);
        acc[3][0] = fmaf(a0.w, b.x, acc[3][0]); acc[3][1] = fmaf(a0.w, b.y, acc[3][1]);
        acc[3][2] = fmaf(a0.w, b.z, acc[3][2]); acc[3][3] = fmaf(a0.w, b.w, acc[3][3]);
        acc[4][0] = fmaf(a1.x, b.x, acc[4][0]); acc[4][1] = fmaf(a1.x, b.y, acc[4][1]);
        acc[4][2] = fmaf(a1.x, b.z, acc[4][2]); acc[4][3] = fmaf(a1.x, b.w, acc[4][3]);
        acc[5][0] = fmaf(a1.y, b.x, acc[5][0]); acc[5][1] = fmaf(a1.y, b.y, acc[5][1]);
        acc[5][2] = fmaf(a1.y, b.z, acc[5][2]); acc[5][3] = fmaf(a1.y, b.w, acc[5][3]);
        acc[6][0] = fmaf(a1.z, b.x, acc[6][0]); acc[6][1] = fmaf(a1.z, b.y, acc[6][1]);
        acc[6][2] = fmaf(a1.z, b.z, acc[6][2]); acc[6][3] = fmaf(a1.z, b.w, acc[6][3]);
        acc[7][0] = fmaf(a1.w, b.x, acc[7][0]); acc[7][1] = fmaf(a1.w, b.y, acc[7][1]);
        acc[7][2] = fmaf(a1.w, b.z, acc[7][2]); acc[7][3] = fmaf(a1.w, b.w, acc[7][3]);
    }

    float bj[4] = {0.f, 0.f, 0.f, 0.f};
    if (bias) {
#pragma unroll
        for (int j = 0; j < 4; j++) bj[j] = bias[col0 + (tx << 2) + j];
    }
#pragma unroll
    for (int i = 0; i < 8; i++) {
        int r = row0 + (ty << 3) + i;
        if (r >= M) continue;
        float4 v;
        float* pv = &v.x;
#pragma unroll
        for (int j = 0; j < 4; j++) {
            float val = acc[i][j] + bj[j];
            if (ACT == 1) val = val / (1.0f + expf(-val));
            pv[j] = val;
        }
        *(float4*)&C[(size_t)r * N + col0 + (tx << 2)] = v;
    }
}

// ---------------- ctx A-operand builder -------------------------------------
__device__ __forceinline__ float4 ctx_load(const float* __restrict__ q,
                                           const float* __restrict__ mumix,
                                           int n, int k, bool valid) {
    if (!valid) return make_float4(0.f, 0.f, 0.f, 0.f);
    if (k < 128) return *(const float4*)&q[(size_t)n * 128 + k];
    int c = k - 128;
    const float* b = mumix + (size_t)n * 768;
    float4 v0 = *(const float4*)&b[c];
    float4 v1 = *(const float4*)&b[256 + c];
    float4 v2 = *(const float4*)&b[512 + c];
    float4 r;
    r.x = sqrtf(v0.x * v0.x + v1.x * v1.x + v2.x * v2.x + 1e-8f);
    r.y = sqrtf(v0.y * v0.y + v1.y * v1.y + v2.y * v2.y + 1e-8f);
    r.z = sqrtf(v0.z * v0.z + v1.z * v1.z + v2.z * v2.z + 1e-8f);
    r.w = sqrtf(v0.w * v0.w + v1.w * v1.w + v2.w * v2.w + 1e-8f);
    return r;
}

// ---------------- ctx GEMM: h = silu(ctx @ W + b), ctx built on the fly ------
__global__ void __launch_bounds__(256)
gemm_ctx(const float* __restrict__ q, const float* __restrict__ mumix,
         const float* __restrict__ W, const float* __restrict__ bias,
         float* __restrict__ C, int M) {
    const int Nn = 128, K = 256;
    __shared__ float As[2][32][68];
    __shared__ float Bs[2][32][68];
    const int tid  = threadIdx.x;
    const int row0 = blockIdx.y * 64;
    const int col0 = blockIdx.x * 64;
    const int tx = tid & 15, ty = tid >> 4;

    int ar0 = tid >> 3,          ak0 = (tid & 7) << 2;
    int ar1 = (tid + 256) >> 3;
    int br0 = tid >> 4,          bc0 = (tid & 15) << 2;
    int br1 = (tid + 256) >> 4;

    const bool av0 = (row0 + ar0) < M;
    const bool av1 = (row0 + ar1) < M;
    const float* Wp0 = W + (size_t)br0 * Nn + col0 + bc0;
    const float* Wp1 = W + (size_t)br1 * Nn + col0 + bc0;

    float4 a0 = ctx_load(q, mumix, row0 + ar0, ak0, av0);
    float4 a1 = ctx_load(q, mumix, row0 + ar1, ak0, av1);
    float4 b0 = *(const float4*)Wp0;
    float4 b1 = *(const float4*)Wp1;
    As[0][ak0 + 0][ar0] = a0.x; As[0][ak0 + 1][ar0] = a0.y;
    As[0][ak0 + 2][ar0] = a0.z; As[0][ak0 + 3][ar0] = a0.w;
    As[0][ak0 + 0][ar1] = a1.x; As[0][ak0 + 1][ar1] = a1.y;
    As[0][ak0 + 2][ar1] = a1.z; As[0][ak0 + 3][ar1] = a1.w;
    *(float4*)&Bs[0][br0][bc0] = b0;
    *(float4*)&Bs[0][br1][bc0] = b1;
    __syncthreads();

    float acc[4][4];
#pragma unroll
    for (int i = 0; i < 4; i++)
#pragma unroll
        for (int j = 0; j < 4; j++) acc[i][j] = 0.0f;

    int buf = 0;
    for (int k0 = 32; k0 < K; k0 += 32) {
        a0 = ctx_load(q, mumix, row0 + ar0, k0 + ak0, av0);
        a1 = ctx_load(q, mumix, row0 + ar1, k0 + ak0, av1);
        b0 = *(const float4*)(Wp0 + (size_t)k0 * Nn);
        b1 = *(const float4*)(Wp1 + (size_t)k0 * Nn);
#pragma unroll
        for (int kk = 0; kk < 32; kk++) {
            float4 a = *(const float4*)&As[buf][kk][ty << 2];
            float4 b = *(const float4*)&Bs[buf][kk][tx << 2];
            acc[0][0] = fmaf(a.x, b.x, acc[0][0]); acc[0][1] = fmaf(a.x, b.y, acc[0][1]);
            acc[0][2] = fmaf(a.x, b.z, acc[0][2]); acc[0][3] = fmaf(a.x, b.w, acc[0][3]);
            acc[1][0] = fmaf(a.y, b.x, acc[1][0]); acc[1][1] = fmaf(a.y, b.y, acc[1][1]);
            acc[1][2] = fmaf(a.y, b.z, acc[1][2]); acc[1][3] = fmaf(a.y, b.w, acc[1][3]);
            acc[2][0] = fmaf(a.z, b.x, acc[2][0]); acc[2][1] = fmaf(a.z, b.y, acc[2][1]);
            acc[2][2] = fmaf(a.z, b.z, acc[2][2]); acc[2][3] = fmaf(a.z, b.w, acc[2][3]);
            acc[3][0] = fmaf(a.w, b.x, acc[3][0]); acc[3][1] = fmaf(a.w, b.y, acc[3][1]);
            acc[3][2] = fmaf(a.w, b.z, acc[3][2]); acc[3][3] = fmaf(a.w, b.w, acc[3][3]);
        }
        buf ^= 1;
        As[buf][ak0 + 0][ar0] = a0.x; As[buf][ak0 + 1][ar0] = a0.y;
        As[buf][ak0 + 2][ar0] = a0.z; As[buf][ak0 + 3][ar0] = a0.w;
        As[buf][ak0 + 0][ar1] = a1.x; As[buf][ak0 + 1][ar1] = a1.y;
        As[buf][ak0 + 2][ar1] = a1.z; As[buf][ak0 + 3][ar1] = a1.w;
        *(float4*)&Bs[buf][br0][bc0] = b0;
        *(float4*)&Bs[buf][br1][bc0] = b1;
        __syncthreads();
    }
#pragma unroll
    for (int kk = 0; kk < 32; kk++) {
        float4 a = *(const float4*)&As[buf][kk][ty << 2];
        float4 b = *(const float4*)&Bs[buf][kk][tx << 2];
        acc[0][0] = fmaf(a.x, b.x, acc[0][0]); acc[0][1] = fmaf(a.x, b.y, acc[0][1]);
        acc[0][2] = fmaf(a.x, b.z, acc[0][2]); acc[0][3] = fmaf(a.x, b.w, acc[0][3]);
        acc[1][0] = fmaf(a.y, b.x, acc[1][0]); acc[1][1] = fmaf(a.y, b.y, acc[1][1]);
        acc[1][2] = fmaf(a.y, b.z, acc[1][2]); acc[1][3] = fmaf(a.y, b.w, acc[1][3]);
        acc[2][0] = fmaf(a.z, b.x, acc[2][0]); acc[2][1] = fmaf(a.z, b.y, acc[2][1]);
        acc[2][2] = fmaf(a.z, b.z, acc[2][2]); acc[2][3] = fmaf(a.z, b.w, acc[2][3]);
        acc[3][0] = fmaf(a.w, b.x, acc[3][0]); acc[3][1] = fmaf(a.w, b.y, acc[3][1]);
        acc[3][2] = fmaf(a.w, b.z, acc[3][2]); acc[3][3] = fmaf(a.w, b.w, acc[3][3]);
    }

    float bj[4];
#pragma unroll
    for (int j = 0; j < 4; j++) bj[j] = bias[col0 + (tx << 2) + j];
#pragma unroll
    for (int i = 0; i < 4; i++) {
        int r = row0 + (ty << 2) + i;
        if (r >= M) continue;
        float4 v;
        float* pv = &v.x;
#pragma unroll
        for (int j = 0; j < 4; j++) {
            float val = acc[i][j] + bj[j];
            val = val / (1.0f + expf(-val));
            pv[j] = val;
        }
        *(float4*)&C[(size_t)r * Nn + col0 + (tx << 2)] = v;
    }
}

// ---------------- edge message + segment-sum kernel (general layers) --------
__global__ void __launch_bounds__(128)
edge_kernel(const float* __restrict__ x,
            float* __restrict__ q,
            const float* __restrict__ mu_in,
            float* __restrict__ mu_out,
            const int* __restrict__ idx_j,
            const float* __restrict__ filt_W,
            const float* __restrict__ filt_b,
            int layer, int N) {
    __shared__ __align__(16) float s_phif[EB * NRBF];
    __shared__ float s_dir[EB * 3];
    __shared__ float s_fcut[EB];
    __shared__ int   s_idx[EB];

    int c = threadIdx.x;   // 0..127
    int layOff = layer * 384;
    u64 WQ2[10], WR2[10], WM2[10];
#pragma unroll
    for (int r2 = 0; r2 < 10; r2++) {
        const float* f0 = &filt_W[(2 * r2)     * (NLAYERS * 384) + layOff];
        const float* f1 = &filt_W[(2 * r2 + 1) * (NLAYERS * 384) + layOff];
        WQ2[r2] = pack2(f0[c],       f1[c]);
        WR2[r2] = pack2(f0[128 + c], f1[128 + c]);
        WM2[r2] = pack2(f0[256 + c], f1[256 + c]);
    }
    float FBq = filt_b[layOff + c];
    float FBr = filt_b[layOff + 128 + c];
    float FBm = filt_b[layOff + 256 + c];

    int node = blockIdx.x;
    if (node >= N) return;
    int e0 = g_rowptr[node], e1 = g_rowptr[node + 1];
    float accq = 0.f, am0 = 0.f, am1 = 0.f, am2 = 0.f;

    for (int eb = e0; eb < e1; eb += EB) {
        int cnt = min(EB, e1 - eb);
        __syncthreads();
        for (int s = c; s < cnt * 5; s += 128)
            *(float4*)&s_phif[s << 2] = *(const float4*)&g_phif[(size_t)eb * NRBF + (s << 2)];
        if (c < cnt * 3) s_dir[c] = g_dir[(size_t)eb * 3 + c];
        if (c < cnt) { s_fcut[c] = g_fcut[eb + c]; s_idx[c] = idx_j[eb + c]; }
        __syncthreads();

        for (int i = 0; i < cnt; i++) {
            int j = s_idx[i];
            const float* xr = &x[(size_t)j * 384];
            const float* mj = &mu_in[(size_t)j * 384];
            float xq = xr[c], xR = xr[128 + c], xM = xr[256 + c];
            float m0 = mj[c], m1 = mj[128 + c], m2 = mj[256 + c];
            u64 pp[10];
            const ulonglong2* pv = (const ulonglong2*)&s_phif[i * NRBF];
#pragma unroll
            for (int v = 0; v < 5; v++) {
                ulonglong2 tt2 = pv[v];
                pp[2 * v]     = tt2.x;
                pp[2 * v + 1] = tt2.y;
            }
            u64 aq = 0ull, ar = 0ull, am = 0ull;
#pragma unroll
            for (int r = 0; r < 10; r++) {
                aq = ffma2(pp[r], WQ2[r], aq);
                ar = ffma2(pp[r], WR2[r], ar);
                am = ffma2(pp[r], WM2[r], am);
            }
            float fc = s_fcut[i];
            float2 fq = unpack2(aq), fr = unpack2(ar), fm = unpack2(am);
            float Wq = fmaf(fc, FBq, fq.x + fq.y);
            float Wr = fmaf(fc, FBr, fr.x + fr.y);
            float Wm = fmaf(fc, FBm, fm.x + fm.y);

            float d0 = s_dir[i * 3 + 0], d1 = s_dir[i * 3 + 1], d2 = s_dir[i * 3 + 2];
            accq = fmaf(Wq, xq, accq);
            float tt  = Wr * xR;
            float wmx = Wm * xM;
            am0 = fmaf(tt, d0, fmaf(wmx, m0, am0));
            am1 = fmaf(tt, d1, fmaf(wmx, m1, am1));
            am2 = fmaf(tt, d2, fmaf(wmx, m2, am2));
        }
    }
    q[(size_t)node * 128 + c] += accq;
    size_t mb = (size_t)node * 384;
    mu_out[mb + c]       = mu_in[mb + c]       + am0;
    mu_out[mb + 128 + c] = mu_in[mb + 128 + c] + am1;
    mu_out[mb + 256 + c] = mu_in[mb + 256 + c] + am2;
}

// ---------------- layer-0 edge kernel: mu_in == 0 everywhere ----------------
__global__ void __launch_bounds__(128)
edge0_kernel(const float* __restrict__ x,
             float* __restrict__ q,
             float* __restrict__ mu_out,
             const int* __restrict__ idx_j,
             const float* __restrict__ filt_W,
             const float* __restrict__ filt_b,
             int N) {
    __shared__ __align__(16) float s_phif[EB * NRBF];
    __shared__ float s_dir[EB * 3];
    __shared__ float s_fcut[EB];
    __shared__ int   s_idx[EB];

    int c = threadIdx.x;
    u64 WQ2[10], WR2[10];
#pragma unroll
    for (int r2 = 0; r2 < 10; r2++) {
        const float* f0 = &filt_W[(2 * r2)     * (NLAYERS * 384)];
        const float* f1 = &filt_W[(2 * r2 + 1) * (NLAYERS * 384)];
        WQ2[r2] = pack2(f0[c],       f1[c]);
        WR2[r2] = pack2(f0[128 + c], f1[128 + c]);
    }
    float FBq = filt_b[c];
    float FBr = filt_b[128 + c];

    int node = blockIdx.x;
    if (node >= N) return;
    int e0 = g_rowptr[node], e1 = g_rowptr[node + 1];
    float accq = 0.f, am0 = 0.f, am1 = 0.f, am2 = 0.f;

    for (int eb = e0; eb < e1; eb += EB) {
        int cnt = min(EB, e1 - eb);
        __syncthreads();
        for (int s = c; s < cnt * 5; s += 128)
            *(float4*)&s_phif[s << 2] = *(const float4*)&g_phif[(size_t)eb * NRBF + (s << 2)];
        if (c < cnt * 3) s_dir[c] = g_dir[(size_t)eb * 3 + c];
        if (c < cnt) { s_fcut[c] = g_fcut[eb + c]; s_idx[c] = idx_j[eb + c]; }
        __syncthreads();

        for (int i = 0; i < cnt; i++) {
            int j = s_idx[i];
            const float* xr = &x[(size_t)j * 384];
            float xq = xr[c], xR = xr[128 + c];
            const u64* pv = (const u64*)&s_phif[i * NRBF];
            u64 aq = 0ull, ar = 0ull;
#pragma unroll
            for (int r = 0; r < 10; r++) {
                u64 pr = pv[r];
                aq = ffma2(pr, WQ2[r], aq);
                ar = ffma2(pr, WR2[r], ar);
            }
            float fc = s_fcut[i];
            float2 fq = unpack2(aq), fr = unpack2(ar);
            float Wq = fmaf(fc, FBq, fq.x + fq.y);
            float Wr = fmaf(fc, FBr, fr.x + fr.y);

            float d0 = s_dir[i * 3 + 0], d1 = s_dir[i * 3 + 1], d2 = s_dir[i * 3 + 2];
            accq = fmaf(Wq, xq, accq);
            float tt = Wr * xR;
            am0 = fmaf(tt, d0, am0);
            am1 = fmaf(tt, d1, am1);
            am2 = fmaf(tt, d2, am2);
        }
    }
    q[(size_t)node * 128 + c] += accq;
    size_t mb = (size_t)node * 384;
    mu_out[mb + c]       = am0;
    mu_out[mb + 128 + c] = am1;
    mu_out[mb + 256 + c] = am2;
}

// ---------------- final per-node update (s computed inline) ----------------
__global__ void epi2_kernel(float* __restrict__ q, float* __restrict__ mu, int N) {
    int t = blockIdx.x * blockDim.x + threadIdx.x;
    if (t >= N * 128) return;
    int n = t >> 7, c = t & 127;
    const float* xr = &g_x[(size_t)n * 384];
    float dq   = xr[c];
    float dmu  = xr[128 + c];
    float dqmu = xr[256 + c];
    const float* mm = &g_mumix[(size_t)n * 768];
    float v0 = mm[c],       v1 = mm[256 + c], v2 = mm[512 + c];
    float w0 = mm[128 + c], w1 = mm[384 + c], w2 = mm[640 + c];
    float s = v0 * w0 + v1 * w1 + v2 * w2;
    q[t] += dq + dqmu * s;
    size_t mb = (size_t)n * 384;
    mu[mb + c]       += dmu * w0;
    mu[mb + 128 + c] += dmu * w1;
    mu[mb + 256 + c] += dmu * w2;
}

// ---------------- host launch ----------------
extern "C" void kernel_launch(void* const* d_in, const int* in_sizes, int n_in,
                              void* d_out, int out_size) {
    const int*   an     = (const int*)  d_in[0];
    const float* r_ij   = (const float*)d_in[1];
    const int*   idx_i  = (const int*)  d_in[2];
    const int*   idx_j  = (const int*)  d_in[3];
    const float* emb    = (const float*)d_in[4];
    const float* filt_W = (const float*)d_in[5];
    const float* filt_b = (const float*)d_in[6];
    const float* int_W1 = (const float*)d_in[7];
    const float* int_b1 = (const float*)d_in[8];
    const float* int_W2 = (const float*)d_in[9];
    const float* int_b2 = (const float*)d_in[10];
    const float* mix_W1 = (const float*)d_in[11];
    const float* mix_b1 = (const float*)d_in[12];
    const float* mix_W2 = (const float*)d_in[13];
    const float* mix_b2 = (const float*)d_in[14];
    const float* mux_W  = (const float*)d_in[15];

    int N = in_sizes[0];
    int E = in_sizes[3];

    float* q      = (float*)d_out;          // [N,128]
    float* mu_out = q + (size_t)N * 128;    // [N,3,128]

    void* pA; cudaGetSymbolAddress(&pA, g_muA);  float* muA  = (float*)pA;
    void* pH; cudaGetSymbolAddress(&pH, g_h);    float* h    = (float*)pH;
    void* pX; cudaGetSymbolAddress(&pX, g_x);    float* xbuf = (float*)pX;
    void* pM; cudaGetSymbolAddress(&pM, g_mumix);float* mumix= (float*)pM;

    const int g128_bytes = G128_SMEM * (int)sizeof(float);   // 51200 B
    cudaFuncSetAttribute(gemm128<0>, cudaFuncAttributeMaxDynamicSharedMemorySize, g128_bytes);

    // fused setup: pre (E threads) + init (N*128) + rowptr (N+1)
    {
        int tot = N * 128 > E ? N * 128 : E;
        if (tot < N + 1) tot = N + 1;
        setup_kernel<<<(tot + 255) / 256, 256>>>(r_ij, idx_i, an, emb, q, E, N);
    }

    for (int l = 0; l < NLAYERS; l++) {
        float* mu_in = (l & 1) ? mu_out : muA;
        float* mu_o  = (l & 1) ? muA    : mu_out;

        // interaction: h = silu(q W1 + b1)
        {
            dim3 g(128 / 64, (N + 63) / 64);
            gemm64<1><<<g, 256>>>(q, int_W1 + (size_t)l * 128 * 128,
                                  int_b1 + l * 128, h, N, 128, 128);
        }
        // x = h W2 + b2  (big tile)
        {
            dim3 g(384 / 64, (N + 127) / 128);
            gemm128<0><<<g, 256, g128_bytes>>>(h, int_W2 + (size_t)l * 128 * 384,
                                               int_b2 + l * 384, xbuf, N, 384, 128);
        }
        // edge messages + segment sum (one block per node)
        if (l == 0) {
            edge0_kernel<<<N, 128>>>(xbuf, q, mu_o, idx_j, filt_W, filt_b, N);
        } else {
            edge_kernel<<<N, 128>>>(xbuf, q, mu_in, mu_o, idx_j,
                                    filt_W, filt_b, l, N);
        }
        // mixing: mumix = mu @ mux_W (no bias), A viewed as [3N,128] (big tile)
        {
            dim3 g(256 / 64, (3 * N + 127) / 128);
            gemm128<0><<<g, 256, g128_bytes>>>(mu_o, mux_W + (size_t)l * 128 * 256,
                                               nullptr, mumix, 3 * N, 256, 128);
        }
        // h = silu(ctx mix_W1 + b1), ctx built on the fly from q + mumix norms
        {
            dim3 g(128 / 64, (N + 63) / 64);
            gemm_ctx<<<g, 256>>>(q, mumix, mix_W1 + (size_t)l * 256 * 128,
                                 mix_b1 + l * 128, h, N);
        }
        // x2 = h mix_W2 + b2 (big tile)
        {
            dim3 g(384 / 64, (N + 127) / 128);
            gemm128<0><<<g, 256, g128_bytes>>>(h, mix_W2 + (size_t)l * 128 * 384,
                                               mix_b2 + l * 384, xbuf, N, 384, 128);
        }
        epi2_kernel<<<((size_t)N * 128 + 255) / 256, 256>>>(q, mu_o, N);
    }
    // layer parity: l=0 in=(zero) out=d_out, l=1 in=d_out out=muA, l=2 in=muA out=d_out.
    // Final q and mu land in d_out. (q lives in d_out throughout.)
}